// round 9
// baseline (speedup 1.0000x reference)
#include <cuda_runtime.h>
#include <cstdint>
#include <math.h>

// ============================================================================
// UnifiedDualPhasorLM — mma.sync tf32 tensor-core GEMMs (sm_80+ path).
//   retrieval rewritten as causal attention: scores = tril(P P^T), P=[cos|sin]
//   R9: mid tile 64x128 (warp-tile 32x64, LDS:HMMA 1.5), split-K cp_w2 with
//   reduction fused into phase_k, dual-residual epilogue.
// ============================================================================

namespace cfg {
constexpr int B = 2, L = 1024, D = 512, K = 32, NL = 4, FF = 2048, V = 32000;
constexpr int M = B * L;      // 2048
constexpr int CS = 2 * K;     // 64
}

// ---------------- scratch ----------------
constexpr size_t SZ_MD  = (size_t)cfg::M * cfg::D;
constexpr size_t OFF_H   = 0;
constexpr size_t OFF_X   = OFF_H   + SZ_MD;
constexpr size_t OFF_T1  = OFF_X   + SZ_MD;
constexpr size_t OFF_V   = OFF_T1  + SZ_MD;
constexpr size_t OFF_RET = OFF_V   + SZ_MD;
constexpr size_t OFF_R2  = OFF_RET + SZ_MD;
constexpr size_t OFF_CP4 = OFF_R2  + SZ_MD;                          // 4 split-K planes
constexpr size_t OFF_CS  = OFF_CP4 + 4 * (size_t)cfg::M * cfg::K;
constexpr size_t OFF_SC  = OFF_CS  + (size_t)cfg::M * cfg::CS;       // 2 planes [L,L]
constexpr size_t OFF_F1  = OFF_SC  + 2 * (size_t)cfg::L * cfg::L;
constexpr size_t SCRATCH_FLOATS = OFF_F1 + (size_t)cfg::M * cfg::FF;

__device__ float g_scratch[SCRATCH_FLOATS];

// ---------------- tf32 helpers ----------------
__device__ __forceinline__ float to_tf32(float x) {
    uint32_t u;
    asm("cvt.rna.tf32.f32 %0, %1;" : "=r"(u) : "f"(x));
    return __uint_as_float(u);
}
__device__ __forceinline__ void mma1688(float* d, const uint32_t* a, const uint32_t* b) {
    asm volatile(
        "mma.sync.aligned.m16n8k8.row.col.f32.tf32.tf32.f32 "
        "{%0,%1,%2,%3}, {%4,%5,%6,%7}, {%8,%9}, {%0,%1,%2,%3};"
        : "+f"(d[0]), "+f"(d[1]), "+f"(d[2]), "+f"(d[3])
        : "r"(a[0]), "r"(a[1]), "r"(a[2]), "r"(a[3]), "r"(b[0]), "r"(b[1]));
}

// ================== tf32 mma.sync GEMM, tile-size templated =================
// C[M,N] = act(A[M,Kd] @ op(B) + bias) (*causal)(*rowscale)(+resid)(+resid2)
// TRANSB=1: B is [N,Kd] row-major. TRANSB=0: B is [Kd,N] row-major.
// Requires M%BM==0, N%BN==0, Kd%32==0 at call sites.
constexpr int SROW = 36;

template<int BM, int BN, int WM, int WN, int TRANSB, int ACT>
__global__ void __launch_bounds__(32 * (BM / WM) * (BN / WN))
mma_gemm_k(const float* __restrict__ A, const float* __restrict__ Bp,
           float* __restrict__ C, int M, int N, int Kd,
           const float* __restrict__ bias, const float* __restrict__ resid,
           const float* __restrict__ resid2,
           int causal, int rowscale, float kf,
           long sAz, long sBz, long sCz)
{
    constexpr int WARPS_M = BM / WM;
    constexpr int THREADS = 32 * WARPS_M * (BN / WN);
    constexpr int MF = WM / 16;
    constexpr int NF = WN / 8;
    constexpr int TILE_FA = BM * SROW;
    constexpr int TILE_FB = BN * SROW;
    constexpr int A_IT = BM * 32 / (4 * THREADS);
    constexpr int B_IT = BN * 32 / (4 * THREADS);
    constexpr int KGRP = THREADS / BN;          // groups for TRANSB=0 ldg
    constexpr int KPG  = 32 / KGRP;             // k per group
    constexpr int Z_IT = BM * BN / (4 * THREADS);

    extern __shared__ float smf[];
    float* sA = smf;                   // [2][BM][SROW]
    float* sB = smf + 2 * TILE_FA;     // [2][BN][SROW]

    A  += (size_t)blockIdx.z * sAz;
    Bp += (size_t)blockIdx.z * sBz;
    C  += (size_t)blockIdx.z * sCz;
    if (resid)  resid  += (size_t)blockIdx.z * sCz;
    if (resid2) resid2 += (size_t)blockIdx.z * sCz;

    const int tid  = threadIdx.x;
    const int lane = tid & 31;
    const int wid  = tid >> 5;
    const int wm   = wid % WARPS_M;
    const int wn   = wid / WARPS_M;
    const int gl   = lane >> 2;      // groupID (0..7)
    const int tl   = lane & 3;       // thread in group (0..3)
    const int bm = blockIdx.y * BM;
    const int bn = blockIdx.x * BN;

    // fully-masked causal tile -> zeros
    if (causal && bn > bm + BM - 1) {
#pragma unroll
        for (int it = 0; it < Z_IT; it++) {
            int idx = tid + it * THREADS;
            int m = idx / (BN / 4), nc = (idx % (BN / 4)) * 4;
            *(float4*)(C + (size_t)(bm + m) * N + bn + nc) = make_float4(0.f, 0.f, 0.f, 0.f);
        }
        return;
    }

    float4 ra[A_IT];
    float4 rb4[B_IT];        // TRANSB=1 staging
    float  rbk[KPG];         // TRANSB=0 staging

    auto ldgA = [&](int k0) {
#pragma unroll
        for (int it = 0; it < A_IT; it++) {
            int idx = tid + it * THREADS;
            float4 v = *(const float4*)(A + (size_t)(bm + (idx >> 3)) * Kd + k0 + (idx & 7) * 4);
            v.x = to_tf32(v.x); v.y = to_tf32(v.y); v.z = to_tf32(v.z); v.w = to_tf32(v.w);
            ra[it] = v;
        }
    };
    auto stsA = [&](int s) {
        float* dst = sA + s * TILE_FA;
#pragma unroll
        for (int it = 0; it < A_IT; it++) {
            int idx = tid + it * THREADS;
            *(float4*)(dst + (idx >> 3) * SROW + (idx & 7) * 4) = ra[it];
        }
    };
    auto ldgB = [&](int k0) {
        if (TRANSB) {
#pragma unroll
            for (int it = 0; it < B_IT; it++) {
                int idx = tid + it * THREADS;
                float4 v = *(const float4*)(Bp + (size_t)(bn + (idx >> 3)) * Kd + k0 + (idx & 7) * 4);
                v.x = to_tf32(v.x); v.y = to_tf32(v.y); v.z = to_tf32(v.z); v.w = to_tf32(v.w);
                rb4[it] = v;
            }
        } else {
            int n = tid % BN, kh = (tid / BN) * KPG;
#pragma unroll
            for (int j = 0; j < KPG; j++)
                rbk[j] = to_tf32(Bp[(size_t)(k0 + kh + j) * N + bn + n]);
        }
    };
    auto stsB = [&](int s) {
        float* dst = sB + s * TILE_FB;
        if (TRANSB) {
#pragma unroll
            for (int it = 0; it < B_IT; it++) {
                int idx = tid + it * THREADS;
                *(float4*)(dst + (idx >> 3) * SROW + (idx & 7) * 4) = rb4[it];
            }
        } else {
            int n = tid % BN, kh = (tid / BN) * KPG;
#pragma unroll
            for (int g = 0; g < KPG / 4; g++)
                *(float4*)(dst + n * SROW + kh + g * 4) =
                    make_float4(rbk[4*g], rbk[4*g+1], rbk[4*g+2], rbk[4*g+3]);
        }
    };

    float acc[MF][NF][4];
#pragma unroll
    for (int i = 0; i < MF; i++)
#pragma unroll
        for (int j = 0; j < NF; j++)
#pragma unroll
            for (int r = 0; r < 4; r++) acc[i][j][r] = 0.f;

    const int CHUNKS = Kd >> 5;

    // prologue
    ldgA(0); ldgB(0);
    stsA(0); stsB(0);
    __syncthreads();

    int buf = 0;
    for (int c = 0; c < CHUNKS; c++) {
        const bool more = (c + 1 < CHUNKS);
        if (more) { ldgA((c + 1) << 5); ldgB((c + 1) << 5); }

        const float* cA = sA + buf * TILE_FA;
        const float* cB = sB + buf * TILE_FB;
#pragma unroll
        for (int ks = 0; ks < 4; ks++) {
            const int kk = ks * 8 + tl;
            uint32_t av[MF][4], bv[NF][2];
#pragma unroll
            for (int mf = 0; mf < MF; mf++) {
                int mr = wm * WM + mf * 16 + gl;
                av[mf][0] = __float_as_uint(cA[ mr      * SROW + kk    ]);
                av[mf][1] = __float_as_uint(cA[(mr + 8) * SROW + kk    ]);
                av[mf][2] = __float_as_uint(cA[ mr      * SROW + kk + 4]);
                av[mf][3] = __float_as_uint(cA[(mr + 8) * SROW + kk + 4]);
            }
#pragma unroll
            for (int nf = 0; nf < NF; nf++) {
                int nr = wn * WN + nf * 8 + gl;
                bv[nf][0] = __float_as_uint(cB[nr * SROW + kk    ]);
                bv[nf][1] = __float_as_uint(cB[nr * SROW + kk + 4]);
            }
#pragma unroll
            for (int mf = 0; mf < MF; mf++)
#pragma unroll
                for (int nf = 0; nf < NF; nf++)
                    mma1688(acc[mf][nf], av[mf], bv[nf]);
        }

        if (more) {
            stsA(buf ^ 1); stsB(buf ^ 1);
            __syncthreads();
            buf ^= 1;
        }
    }

    // epilogue: c0=(g,2t) c1=(g,2t+1) c2=(g+8,2t) c3=(g+8,2t+1)
#pragma unroll
    for (int mf = 0; mf < MF; mf++)
#pragma unroll
        for (int nf = 0; nf < NF; nf++) {
            int m0 = bm + wm * WM + mf * 16 + gl;
            int n0 = bn + wn * WN + nf * 8 + tl * 2;
            float b0 = 0.f, b1 = 0.f;
            if (bias) { b0 = __ldg(bias + n0); b1 = __ldg(bias + n0 + 1); }
#pragma unroll
            for (int rr = 0; rr < 2; rr++) {
                int m = m0 + rr * 8;
                float v0 = acc[mf][nf][rr * 2 + 0] + b0;
                float v1 = acc[mf][nf][rr * 2 + 1] + b1;
                if (ACT == 1)      { v0 = tanhf(v0); v1 = tanhf(v1); }
                else if (ACT == 2) {
                    v0 = 0.5f * v0 * (1.f + erff(v0 * 0.7071067811865476f));
                    v1 = 0.5f * v1 * (1.f + erff(v1 * 0.7071067811865476f));
                }
                if (causal) { if (n0 > m) v0 = 0.f; if (n0 + 1 > m) v1 = 0.f; }
                if (rowscale) {
                    float rs = rsqrtf((float)(m + 1) * kf);
                    v0 *= rs; v1 *= rs;
                }
                if (resid) {
                    float2 rv = *(const float2*)(resid + (size_t)m * N + n0);
                    v0 += rv.x; v1 += rv.y;
                }
                if (resid2) {
                    float2 rv = *(const float2*)(resid2 + (size_t)m * N + n0);
                    v0 += rv.x; v1 += rv.y;
                }
                *(float2*)(C + (size_t)m * N + n0) = make_float2(v0, v1);
            }
        }
}

enum { ACT_NONE = 0, ACT_TANH = 1, ACT_GELU = 2, ACT_TANHPI = 3 };

// big: 128x128 tiles, 8 warps; mid: 64x128 tiles, 4 warps (warp tile 32x64)
template<int TRANSB, int ACT>
static void mm(const float* A, const float* Bp, float* C, int M, int N, int Kd,
               const float* bias, const float* resid, const float* resid2 = nullptr,
               int causal = 0, int rowscale = 0, float kf = 32.f,
               int gz = 1, long sAz = 0, long sBz = 0, long sCz = 0)
{
    long big_blocks = (long)(M / 128) * (N / 128) * gz;
    if (N % 128 == 0 && big_blocks >= 148) {
        constexpr int SM_BYTES = 2 * (128 + 128) * SROW * 4;   // 73728
        cudaFuncSetAttribute(mma_gemm_k<128, 128, 32, 64, TRANSB, ACT>,
                             cudaFuncAttributeMaxDynamicSharedMemorySize, SM_BYTES);
        dim3 g(N / 128, M / 128, gz);
        mma_gemm_k<128, 128, 32, 64, TRANSB, ACT><<<g, 256, SM_BYTES>>>(
            A, Bp, C, M, N, Kd, bias, resid, resid2, causal, rowscale, kf, sAz, sBz, sCz);
    } else {
        constexpr int SM_BYTES = 2 * (64 + 128) * SROW * 4;    // 55296
        cudaFuncSetAttribute(mma_gemm_k<64, 128, 32, 64, TRANSB, ACT>,
                             cudaFuncAttributeMaxDynamicSharedMemorySize, SM_BYTES);
        dim3 g(N / 128, M / 64, gz);
        mma_gemm_k<64, 128, 32, 64, TRANSB, ACT><<<g, 128, SM_BYTES>>>(
            A, Bp, C, M, N, Kd, bias, resid, resid2, causal, rowscale, kf, sAz, sBz, sCz);
    }
}

// ================== small helpers (verified) ================================
__device__ __forceinline__ float block_sum(float v, float* red) {
    int lane = threadIdx.x & 31, w = threadIdx.x >> 5;
#pragma unroll
    for (int o = 16; o; o >>= 1) v += __shfl_xor_sync(0xffffffffu, v, o);
    __syncthreads();
    if (lane == 0) red[w] = v;
    __syncthreads();
    float t = (threadIdx.x < (blockDim.x >> 5)) ? red[threadIdx.x] : 0.f;
    if (w == 0) {
#pragma unroll
        for (int o = 16; o; o >>= 1) t += __shfl_xor_sync(0xffffffffu, t, o);
        if (lane == 0) red[32] = t;
    }
    __syncthreads();
    return red[32];
}

__global__ void ln_k(const float* __restrict__ X, float* __restrict__ Y,
                     const float* __restrict__ g, const float* __restrict__ b, int Dn)
{
    __shared__ float red[33];
    int row = blockIdx.x;
    const float* x = X + (size_t)row * Dn;
    float s = 0.f;
    for (int d = threadIdx.x; d < Dn; d += blockDim.x) s += x[d];
    float mean = block_sum(s, red) / (float)Dn;
    float v = 0.f;
    for (int d = threadIdx.x; d < Dn; d += blockDim.x) { float t = x[d] - mean; v += t * t; }
    float var = block_sum(v, red) / (float)Dn;
    float inv = rsqrtf(var + 1e-5f);
    float* y = Y + (size_t)row * Dn;
    for (int d = threadIdx.x; d < Dn; d += blockDim.x)
        y[d] = (x[d] - mean) * inv * g[d] + b[d];
}

__global__ void gather_k(const int* __restrict__ tok, const float* __restrict__ emb,
                         float* __restrict__ h, int n, int Dn)
{
    int i = blockIdx.x * blockDim.x + threadIdx.x;
    int total = n * (Dn / 4);
    if (i >= total) return;
    int row = i / (Dn / 4), c = i % (Dn / 4);
    ((float4*)h)[i] = ((const float4*)(emb + (size_t)tok[row] * Dn))[c];
}

// phase_k with fused split-K reduction + bias + pi*tanh:
// cp_raw = sum_z cp4[z*MK + i] + b2[k];  cp = pi*tanh(cp_raw)
__global__ void phase_k(const float* __restrict__ cp4, const float* __restrict__ b2,
                        float* __restrict__ cs,
                        const float* __restrict__ ps_arr, const float* __restrict__ cs_arr,
                        int layer, int Ln, int Kn, int total)
{
    int i = blockIdx.x * blockDim.x + threadIdx.x;
    if (i >= total) return;
    int k  = i % Kn;
    int l  = (i / Kn) % Ln;
    int bl = i / Kn;
    float s = cp4[i] + cp4[total + i] + cp4[2 * total + i] + cp4[3 * total + i] + b2[k];
    float cpv = 3.14159274101257324f * tanhf(s);
    float freq = (float)exp(-(double)k / (double)Kn * 9.210340371976184);
    float pos  = __fmul_rn((float)l, freq);
    float tp   = __fadd_rn(__fmul_rn(ps_arr[layer], pos),
                           __fmul_rn(cs_arr[layer], cpv));
    float* o = cs + (size_t)bl * (2 * Kn);
    o[k]      = cosf(tp);
    o[Kn + k] = sinf(tp);
}

// ---- fp32 split-K GEMM for cp_w2 (N=32): raw partials, 4-way K split ----
template<int BM, int BN, int BK, int TM, int TN>
__global__ void gemm_f32_splitk_k(const float* __restrict__ A, const float* __restrict__ Bp,
                                  float* __restrict__ C, int M, int N, int Kd, int split)
{
    constexpr int THREADS = (BM / TM) * (BN / TN);
    __shared__ float As[BK][BM + 4];
    __shared__ float Bs[BK][BN + 4];
    const int tid = threadIdx.x;
    const int bm = blockIdx.y * BM, bn = blockIdx.x * BN;
    const int z  = blockIdx.z;
    const int kslice = Kd / split;
    const int kbeg = z * kslice, kend = kbeg + kslice;
    const int tx = tid % (BN / TN), ty = tid / (BN / TN);

    float acc[TM][TN];
#pragma unroll
    for (int i = 0; i < TM; i++)
#pragma unroll
        for (int j = 0; j < TN; j++) acc[i][j] = 0.f;

    constexpr int A_IT = (BM * BK) / (4 * THREADS);
    constexpr int B_IT = (BK * BN) / (4 * THREADS);

    for (int k0 = kbeg; k0 < kend; k0 += BK) {
#pragma unroll
        for (int it = 0; it < A_IT; it++) {
            int t = tid + it * THREADS;
            int r = t / (BK / 4), c4 = (t % (BK / 4)) * 4;
            int m = bm + r;
            float4 v = make_float4(0.f, 0.f, 0.f, 0.f);
            if (m < M) v = *(const float4*)(A + (size_t)m * Kd + k0 + c4);
            As[c4 + 0][r] = v.x; As[c4 + 1][r] = v.y;
            As[c4 + 2][r] = v.z; As[c4 + 3][r] = v.w;
        }
#pragma unroll
        for (int it = 0; it < B_IT; it++) {
            int t = tid + it * THREADS;
            int kr = t / (BN / 4), nc = (t % (BN / 4)) * 4;
            float4 v = make_float4(0.f, 0.f, 0.f, 0.f);
            if (bn + nc < N) v = *(const float4*)(Bp + (size_t)(k0 + kr) * N + bn + nc);
            *(float4*)&Bs[kr][nc] = v;
        }
        __syncthreads();
#pragma unroll
        for (int kk = 0; kk < BK; kk++) {
            float a[TM], b[TN];
#pragma unroll
            for (int i = 0; i < TM; i++) a[i] = As[kk][ty * TM + i];
#pragma unroll
            for (int j = 0; j < TN; j++) b[j] = Bs[kk][tx * TN + j];
#pragma unroll
            for (int i = 0; i < TM; i++)
#pragma unroll
                for (int j = 0; j < TN; j++)
                    acc[i][j] = fmaf(a[i], b[j], acc[i][j]);
        }
        __syncthreads();
    }
    float* Cz = C + (size_t)z * M * N;
#pragma unroll
    for (int i = 0; i < TM; i++) {
        int m = bm + ty * TM + i;
        if (m >= M) continue;
#pragma unroll
        for (int j = 0; j < TN; j++) {
            int n = bn + tx * TN + j;
            if (n >= N) continue;
            Cz[(size_t)m * N + n] = acc[i][j];
        }
    }
}

// ---------------- orchestration ----------------
extern "C" void kernel_launch(void* const* d_in, const int* in_sizes, int n_in,
                              void* d_out, int out_size)
{
    using namespace cfg;
    const int*   tokens        = (const int*)  d_in[0];
    const float* embed         = (const float*)d_in[1];
    const float* ln1_g         = (const float*)d_in[2];
    const float* ln1_b         = (const float*)d_in[3];
    const float* cp_w1         = (const float*)d_in[4];
    const float* cp_b1         = (const float*)d_in[5];
    const float* cp_w2         = (const float*)d_in[6];
    const float* cp_b2         = (const float*)d_in[7];
    const float* pos_scale     = (const float*)d_in[8];
    const float* content_scale = (const float*)d_in[9];
    const float* val_w         = (const float*)d_in[10];
    const float* val_b         = (const float*)d_in[11];
    const float* oln_g         = (const float*)d_in[12];
    const float* oln_b         = (const float*)d_in[13];
    const float* out_w         = (const float*)d_in[14];
    const float* out_b         = (const float*)d_in[15];
    const float* ln2_g         = (const float*)d_in[16];
    const float* ln2_b         = (const float*)d_in[17];
    const float* ffn_w1        = (const float*)d_in[18];
    const float* ffn_b1        = (const float*)d_in[19];
    const float* ffn_w2        = (const float*)d_in[20];
    const float* ffn_b2        = (const float*)d_in[21];
    const float* no_g          = (const float*)d_in[22];
    const float* no_b          = (const float*)d_in[23];
    const float* head_b        = (const float*)d_in[24];
    float* out = (float*)d_out;

    float* base = nullptr;
    cudaGetSymbolAddress((void**)&base, g_scratch);
    float* h   = base + OFF_H;
    float* x   = base + OFF_X;
    float* t1  = base + OFF_T1;
    float* v   = base + OFF_V;
    float* ret = base + OFF_RET;
    float* r2  = base + OFF_R2;
    float* cp4 = base + OFF_CP4;
    float* cs  = base + OFF_CS;
    float* sc  = base + OFF_SC;
    float* f1  = base + OFF_F1;

    gather_k<<<(M * D / 4 + 255) / 256, 256>>>(tokens, embed, h, M, D);

    for (int i = 0; i < NL; i++) {
        ln_k<<<M, 256>>>(h, x, ln1_g + (size_t)i * D, ln1_b + (size_t)i * D, D);
        // t1 = tanh(x @ cp_w1 + b1)      [2048,512,512] -> mid 64x128, 128 blocks
        mm<0, ACT_TANH>(x, cp_w1 + (size_t)i * D * D, t1, M, D, D,
                        cp_b1 + (size_t)i * D, nullptr);
        // cp partials = t1 @ cp_w2 (split-K x4)   grid (1,64,4) = 256 blocks
        {
            dim3 g(K / 32, M / 32, 4);
            gemm_f32_splitk_k<32, 32, 32, 2, 2><<<g, 256>>>(
                t1, cp_w2 + (size_t)i * D * K, cp4, M, K, D, 4);
        }
        // v = x @ val_w + val_b
        mm<0, ACT_NONE>(x, val_w + (size_t)i * D * D, v, M, D, D,
                        val_b + (size_t)i * D, nullptr);
        // cs = [cos|sin] with fused split-K reduce + bias + pi*tanh
        phase_k<<<(B * L * K + 255) / 256, 256>>>(cp4, cp_b2 + (size_t)i * K, cs,
                                                  pos_scale, content_scale,
                                                  i, L, K, B * L * K);
        // scores = tril(P P^T)  [L,L,64] x2 -> mid 64x128, 256 blocks
        mm<1, ACT_NONE>(cs, cs, sc, L, L, CS, nullptr, nullptr, nullptr,
                        /*causal=*/1, 0, 0.f,
                        /*gz=*/B, (long)L * CS, (long)L * CS, (long)L * L);
        // ret = (scores @ v) * rsqrt((m+1)*K)  [L,D,L] x2 -> mid, 128 blocks
        mm<0, ACT_NONE>(sc, v, ret, L, D, L, nullptr, nullptr, nullptr,
                        0, /*rowscale=*/1, (float)K,
                        /*gz=*/B, (long)L * L, (long)L * D, (long)L * D);
        ln_k<<<M, 256>>>(ret, r2, oln_g + (size_t)i * D, oln_b + (size_t)i * D, D);
        // h = (h + x) + r2 @ out_w + out_b    (dual residual)
        mm<0, ACT_NONE>(r2, out_w + (size_t)i * D * D, h, M, D, D,
                        out_b + (size_t)i * D, h, x);
        ln_k<<<M, 256>>>(h, x, ln2_g + (size_t)i * D, ln2_b + (size_t)i * D, D);
        // f1 = gelu(x @ ffn_w1 + b1)   [2048,2048,512] -> big tiles, 256 blocks
        mm<0, ACT_GELU>(x, ffn_w1 + (size_t)i * D * FF, f1, M, FF, D,
                        ffn_b1 + (size_t)i * FF, nullptr);
        // h = h + f1 @ ffn_w2 + b2     [2048,512,2048] -> mid tiles
        mm<0, ACT_NONE>(f1, ffn_w2 + (size_t)i * FF * D, h, M, D, FF,
                        ffn_b2 + (size_t)i * D, h);
    }

    ln_k<<<M, 256>>>(h, x, no_g, no_b, D);
    // logits = LN(h) @ embed^T + head_b   [2048,32000,512] -> big tiles
    mm<1, ACT_NONE>(x, embed, out, M, V, D, head_b, nullptr);
}

// round 15
// speedup vs baseline: 1.1225x; 1.1225x over previous
#include <cuda_runtime.h>
#include <cstdint>
#include <math.h>

// ============================================================================
// UnifiedDualPhasorLM — mma.sync tf32 tensor-core GEMMs (sm_80+ path).
//   retrieval rewritten as causal attention: scores = tril(P P^T), P=[cos|sin]
//   R10-R15: mid tile 64x64 (R8 config, 256-block chip fill) + split-K cp_w2
//   with reduction fused into phase_k (R9's verified win).
// ============================================================================

namespace cfg {
constexpr int B = 2, L = 1024, D = 512, K = 32, NL = 4, FF = 2048, V = 32000;
constexpr int M = B * L;      // 2048
constexpr int CS = 2 * K;     // 64
}

// ---------------- scratch ----------------
constexpr size_t SZ_MD  = (size_t)cfg::M * cfg::D;
constexpr size_t OFF_H   = 0;
constexpr size_t OFF_X   = OFF_H   + SZ_MD;
constexpr size_t OFF_T1  = OFF_X   + SZ_MD;
constexpr size_t OFF_V   = OFF_T1  + SZ_MD;
constexpr size_t OFF_RET = OFF_V   + SZ_MD;
constexpr size_t OFF_R2  = OFF_RET + SZ_MD;
constexpr size_t OFF_CP4 = OFF_R2  + SZ_MD;                          // 4 split-K planes
constexpr size_t OFF_CS  = OFF_CP4 + 4 * (size_t)cfg::M * cfg::K;
constexpr size_t OFF_SC  = OFF_CS  + (size_t)cfg::M * cfg::CS;       // 2 planes [L,L]
constexpr size_t OFF_F1  = OFF_SC  + 2 * (size_t)cfg::L * cfg::L;
constexpr size_t SCRATCH_FLOATS = OFF_F1 + (size_t)cfg::M * cfg::FF;

__device__ float g_scratch[SCRATCH_FLOATS];

// ---------------- tf32 helpers ----------------
__device__ __forceinline__ float to_tf32(float x) {
    uint32_t u;
    asm("cvt.rna.tf32.f32 %0, %1;" : "=r"(u) : "f"(x));
    return __uint_as_float(u);
}
__device__ __forceinline__ void mma1688(float* d, const uint32_t* a, const uint32_t* b) {
    asm volatile(
        "mma.sync.aligned.m16n8k8.row.col.f32.tf32.tf32.f32 "
        "{%0,%1,%2,%3}, {%4,%5,%6,%7}, {%8,%9}, {%0,%1,%2,%3};"
        : "+f"(d[0]), "+f"(d[1]), "+f"(d[2]), "+f"(d[3])
        : "r"(a[0]), "r"(a[1]), "r"(a[2]), "r"(a[3]), "r"(b[0]), "r"(b[1]));
}

// ================== tf32 mma.sync GEMM, tile-size templated =================
// C[M,N] = act(A[M,Kd] @ op(B) + bias) (*causal)(*rowscale)(+resid)(+resid2)
// TRANSB=1: B is [N,Kd] row-major. TRANSB=0: B is [Kd,N] row-major.
// Requires M%BM==0, N%BN==0, Kd%32==0 at call sites.
constexpr int SROW = 36;

template<int BM, int BN, int WM, int WN, int TRANSB, int ACT>
__global__ void __launch_bounds__(32 * (BM / WM) * (BN / WN))
mma_gemm_k(const float* __restrict__ A, const float* __restrict__ Bp,
           float* __restrict__ C, int M, int N, int Kd,
           const float* __restrict__ bias, const float* __restrict__ resid,
           const float* __restrict__ resid2,
           int causal, int rowscale, float kf,
           long sAz, long sBz, long sCz)
{
    constexpr int WARPS_M = BM / WM;
    constexpr int THREADS = 32 * WARPS_M * (BN / WN);
    constexpr int MF = WM / 16;
    constexpr int NF = WN / 8;
    constexpr int TILE_FA = BM * SROW;
    constexpr int TILE_FB = BN * SROW;
    constexpr int A_IT = BM * 32 / (4 * THREADS);
    constexpr int B_IT = BN * 32 / (4 * THREADS);
    constexpr int KGRP = THREADS / BN;          // groups for TRANSB=0 ldg
    constexpr int KPG  = 32 / KGRP;             // k per group
    constexpr int Z_IT = BM * BN / (4 * THREADS);

    extern __shared__ float smf[];
    float* sA = smf;                   // [2][BM][SROW]
    float* sB = smf + 2 * TILE_FA;     // [2][BN][SROW]

    A  += (size_t)blockIdx.z * sAz;
    Bp += (size_t)blockIdx.z * sBz;
    C  += (size_t)blockIdx.z * sCz;
    if (resid)  resid  += (size_t)blockIdx.z * sCz;
    if (resid2) resid2 += (size_t)blockIdx.z * sCz;

    const int tid  = threadIdx.x;
    const int lane = tid & 31;
    const int wid  = tid >> 5;
    const int wm   = wid % WARPS_M;
    const int wn   = wid / WARPS_M;
    const int gl   = lane >> 2;      // groupID (0..7)
    const int tl   = lane & 3;       // thread in group (0..3)
    const int bm = blockIdx.y * BM;
    const int bn = blockIdx.x * BN;

    // fully-masked causal tile -> zeros
    if (causal && bn > bm + BM - 1) {
#pragma unroll
        for (int it = 0; it < Z_IT; it++) {
            int idx = tid + it * THREADS;
            int m = idx / (BN / 4), nc = (idx % (BN / 4)) * 4;
            *(float4*)(C + (size_t)(bm + m) * N + bn + nc) = make_float4(0.f, 0.f, 0.f, 0.f);
        }
        return;
    }

    float4 ra[A_IT];
    float4 rb4[B_IT];        // TRANSB=1 staging
    float  rbk[KPG];         // TRANSB=0 staging

    auto ldgA = [&](int k0) {
#pragma unroll
        for (int it = 0; it < A_IT; it++) {
            int idx = tid + it * THREADS;
            float4 v = *(const float4*)(A + (size_t)(bm + (idx >> 3)) * Kd + k0 + (idx & 7) * 4);
            v.x = to_tf32(v.x); v.y = to_tf32(v.y); v.z = to_tf32(v.z); v.w = to_tf32(v.w);
            ra[it] = v;
        }
    };
    auto stsA = [&](int s) {
        float* dst = sA + s * TILE_FA;
#pragma unroll
        for (int it = 0; it < A_IT; it++) {
            int idx = tid + it * THREADS;
            *(float4*)(dst + (idx >> 3) * SROW + (idx & 7) * 4) = ra[it];
        }
    };
    auto ldgB = [&](int k0) {
        if (TRANSB) {
#pragma unroll
            for (int it = 0; it < B_IT; it++) {
                int idx = tid + it * THREADS;
                float4 v = *(const float4*)(Bp + (size_t)(bn + (idx >> 3)) * Kd + k0 + (idx & 7) * 4);
                v.x = to_tf32(v.x); v.y = to_tf32(v.y); v.z = to_tf32(v.z); v.w = to_tf32(v.w);
                rb4[it] = v;
            }
        } else {
            int n = tid % BN, kh = (tid / BN) * KPG;
#pragma unroll
            for (int j = 0; j < KPG; j++)
                rbk[j] = to_tf32(Bp[(size_t)(k0 + kh + j) * N + bn + n]);
        }
    };
    auto stsB = [&](int s) {
        float* dst = sB + s * TILE_FB;
        if (TRANSB) {
#pragma unroll
            for (int it = 0; it < B_IT; it++) {
                int idx = tid + it * THREADS;
                *(float4*)(dst + (idx >> 3) * SROW + (idx & 7) * 4) = rb4[it];
            }
        } else {
            int n = tid % BN, kh = (tid / BN) * KPG;
#pragma unroll
            for (int g = 0; g < KPG / 4; g++)
                *(float4*)(dst + n * SROW + kh + g * 4) =
                    make_float4(rbk[4*g], rbk[4*g+1], rbk[4*g+2], rbk[4*g+3]);
        }
    };

    float acc[MF][NF][4];
#pragma unroll
    for (int i = 0; i < MF; i++)
#pragma unroll
        for (int j = 0; j < NF; j++)
#pragma unroll
            for (int r = 0; r < 4; r++) acc[i][j][r] = 0.f;

    const int CHUNKS = Kd >> 5;

    // prologue
    ldgA(0); ldgB(0);
    stsA(0); stsB(0);
    __syncthreads();

    int buf = 0;
    for (int c = 0; c < CHUNKS; c++) {
        const bool more = (c + 1 < CHUNKS);
        if (more) { ldgA((c + 1) << 5); ldgB((c + 1) << 5); }

        const float* cA = sA + buf * TILE_FA;
        const float* cB = sB + buf * TILE_FB;
#pragma unroll
        for (int ks = 0; ks < 4; ks++) {
            const int kk = ks * 8 + tl;
            uint32_t av[MF][4], bv[NF][2];
#pragma unroll
            for (int mf = 0; mf < MF; mf++) {
                int mr = wm * WM + mf * 16 + gl;
                av[mf][0] = __float_as_uint(cA[ mr      * SROW + kk    ]);
                av[mf][1] = __float_as_uint(cA[(mr + 8) * SROW + kk    ]);
                av[mf][2] = __float_as_uint(cA[ mr      * SROW + kk + 4]);
                av[mf][3] = __float_as_uint(cA[(mr + 8) * SROW + kk + 4]);
            }
#pragma unroll
            for (int nf = 0; nf < NF; nf++) {
                int nr = wn * WN + nf * 8 + gl;
                bv[nf][0] = __float_as_uint(cB[nr * SROW + kk    ]);
                bv[nf][1] = __float_as_uint(cB[nr * SROW + kk + 4]);
            }
#pragma unroll
            for (int mf = 0; mf < MF; mf++)
#pragma unroll
                for (int nf = 0; nf < NF; nf++)
                    mma1688(acc[mf][nf], av[mf], bv[nf]);
        }

        if (more) {
            stsA(buf ^ 1); stsB(buf ^ 1);
            __syncthreads();
            buf ^= 1;
        }
    }

    // epilogue: c0=(g,2t) c1=(g,2t+1) c2=(g+8,2t) c3=(g+8,2t+1)
#pragma unroll
    for (int mf = 0; mf < MF; mf++)
#pragma unroll
        for (int nf = 0; nf < NF; nf++) {
            int m0 = bm + wm * WM + mf * 16 + gl;
            int n0 = bn + wn * WN + nf * 8 + tl * 2;
            float b0 = 0.f, b1 = 0.f;
            if (bias) { b0 = __ldg(bias + n0); b1 = __ldg(bias + n0 + 1); }
#pragma unroll
            for (int rr = 0; rr < 2; rr++) {
                int m = m0 + rr * 8;
                float v0 = acc[mf][nf][rr * 2 + 0] + b0;
                float v1 = acc[mf][nf][rr * 2 + 1] + b1;
                if (ACT == 1)      { v0 = tanhf(v0); v1 = tanhf(v1); }
                else if (ACT == 2) {
                    v0 = 0.5f * v0 * (1.f + erff(v0 * 0.7071067811865476f));
                    v1 = 0.5f * v1 * (1.f + erff(v1 * 0.7071067811865476f));
                }
                if (causal) { if (n0 > m) v0 = 0.f; if (n0 + 1 > m) v1 = 0.f; }
                if (rowscale) {
                    float rs = rsqrtf((float)(m + 1) * kf);
                    v0 *= rs; v1 *= rs;
                }
                if (resid) {
                    float2 rv = *(const float2*)(resid + (size_t)m * N + n0);
                    v0 += rv.x; v1 += rv.y;
                }
                if (resid2) {
                    float2 rv = *(const float2*)(resid2 + (size_t)m * N + n0);
                    v0 += rv.x; v1 += rv.y;
                }
                *(float2*)(C + (size_t)m * N + n0) = make_float2(v0, v1);
            }
        }
}

enum { ACT_NONE = 0, ACT_TANH = 1, ACT_GELU = 2, ACT_TANHPI = 3 };

// big: 128x128 tiles, 8 warps; mid: 64x64 tiles, 4 warps (R8 config)
template<int TRANSB, int ACT>
static void mm(const float* A, const float* Bp, float* C, int M, int N, int Kd,
               const float* bias, const float* resid, const float* resid2 = nullptr,
               int causal = 0, int rowscale = 0, float kf = 32.f,
               int gz = 1, long sAz = 0, long sBz = 0, long sCz = 0)
{
    long big_blocks = (long)(M / 128) * (N / 128) * gz;
    if (N % 128 == 0 && big_blocks >= 148) {
        constexpr int SM_BYTES = 2 * (128 + 128) * SROW * 4;   // 73728
        cudaFuncSetAttribute(mma_gemm_k<128, 128, 32, 64, TRANSB, ACT>,
                             cudaFuncAttributeMaxDynamicSharedMemorySize, SM_BYTES);
        dim3 g(N / 128, M / 128, gz);
        mma_gemm_k<128, 128, 32, 64, TRANSB, ACT><<<g, 256, SM_BYTES>>>(
            A, Bp, C, M, N, Kd, bias, resid, resid2, causal, rowscale, kf, sAz, sBz, sCz);
    } else {
        constexpr int SM_BYTES = 2 * (64 + 64) * SROW * 4;     // 36864
        dim3 g(N / 64, M / 64, gz);
        mma_gemm_k<64, 64, 32, 32, TRANSB, ACT><<<g, 128, SM_BYTES>>>(
            A, Bp, C, M, N, Kd, bias, resid, resid2, causal, rowscale, kf, sAz, sBz, sCz);
    }
}

// ================== small helpers (verified) ================================
__device__ __forceinline__ float block_sum(float v, float* red) {
    int lane = threadIdx.x & 31, w = threadIdx.x >> 5;
#pragma unroll
    for (int o = 16; o; o >>= 1) v += __shfl_xor_sync(0xffffffffu, v, o);
    __syncthreads();
    if (lane == 0) red[w] = v;
    __syncthreads();
    float t = (threadIdx.x < (blockDim.x >> 5)) ? red[threadIdx.x] : 0.f;
    if (w == 0) {
#pragma unroll
        for (int o = 16; o; o >>= 1) t += __shfl_xor_sync(0xffffffffu, t, o);
        if (lane == 0) red[32] = t;
    }
    __syncthreads();
    return red[32];
}

__global__ void ln_k(const float* __restrict__ X, float* __restrict__ Y,
                     const float* __restrict__ g, const float* __restrict__ b, int Dn)
{
    __shared__ float red[33];
    int row = blockIdx.x;
    const float* x = X + (size_t)row * Dn;
    float s = 0.f;
    for (int d = threadIdx.x; d < Dn; d += blockDim.x) s += x[d];
    float mean = block_sum(s, red) / (float)Dn;
    float v = 0.f;
    for (int d = threadIdx.x; d < Dn; d += blockDim.x) { float t = x[d] - mean; v += t * t; }
    float var = block_sum(v, red) / (float)Dn;
    float inv = rsqrtf(var + 1e-5f);
    float* y = Y + (size_t)row * Dn;
    for (int d = threadIdx.x; d < Dn; d += blockDim.x)
        y[d] = (x[d] - mean) * inv * g[d] + b[d];
}

__global__ void gather_k(const int* __restrict__ tok, const float* __restrict__ emb,
                         float* __restrict__ h, int n, int Dn)
{
    int i = blockIdx.x * blockDim.x + threadIdx.x;
    int total = n * (Dn / 4);
    if (i >= total) return;
    int row = i / (Dn / 4), c = i % (Dn / 4);
    ((float4*)h)[i] = ((const float4*)(emb + (size_t)tok[row] * Dn))[c];
}

// phase_k with fused split-K reduction + bias + pi*tanh:
// cp_raw = sum_z cp4[z*MK + i] + b2[k];  cp = pi*tanh(cp_raw)
__global__ void phase_k(const float* __restrict__ cp4, const float* __restrict__ b2,
                        float* __restrict__ cs,
                        const float* __restrict__ ps_arr, const float* __restrict__ cs_arr,
                        int layer, int Ln, int Kn, int total)
{
    int i = blockIdx.x * blockDim.x + threadIdx.x;
    if (i >= total) return;
    int k  = i % Kn;
    int l  = (i / Kn) % Ln;
    int bl = i / Kn;
    float s = cp4[i] + cp4[total + i] + cp4[2 * total + i] + cp4[3 * total + i] + b2[k];
    float cpv = 3.14159274101257324f * tanhf(s);
    float freq = (float)exp(-(double)k / (double)Kn * 9.210340371976184);
    float pos  = __fmul_rn((float)l, freq);
    float tp   = __fadd_rn(__fmul_rn(ps_arr[layer], pos),
                           __fmul_rn(cs_arr[layer], cpv));
    float* o = cs + (size_t)bl * (2 * Kn);
    o[k]      = cosf(tp);
    o[Kn + k] = sinf(tp);
}

// ---- fp32 split-K GEMM for cp_w2 (N=32): raw partials, 4-way K split ----
template<int BM, int BN, int BK, int TM, int TN>
__global__ void gemm_f32_splitk_k(const float* __restrict__ A, const float* __restrict__ Bp,
                                  float* __restrict__ C, int M, int N, int Kd, int split)
{
    constexpr int THREADS = (BM / TM) * (BN / TN);
    __shared__ float As[BK][BM + 4];
    __shared__ float Bs[BK][BN + 4];
    const int tid = threadIdx.x;
    const int bm = blockIdx.y * BM, bn = blockIdx.x * BN;
    const int z  = blockIdx.z;
    const int kslice = Kd / split;
    const int kbeg = z * kslice, kend = kbeg + kslice;
    const int tx = tid % (BN / TN), ty = tid / (BN / TN);

    float acc[TM][TN];
#pragma unroll
    for (int i = 0; i < TM; i++)
#pragma unroll
        for (int j = 0; j < TN; j++) acc[i][j] = 0.f;

    constexpr int A_IT = (BM * BK) / (4 * THREADS);
    constexpr int B_IT = (BK * BN) / (4 * THREADS);

    for (int k0 = kbeg; k0 < kend; k0 += BK) {
#pragma unroll
        for (int it = 0; it < A_IT; it++) {
            int t = tid + it * THREADS;
            int r = t / (BK / 4), c4 = (t % (BK / 4)) * 4;
            int m = bm + r;
            float4 v = make_float4(0.f, 0.f, 0.f, 0.f);
            if (m < M) v = *(const float4*)(A + (size_t)m * Kd + k0 + c4);
            As[c4 + 0][r] = v.x; As[c4 + 1][r] = v.y;
            As[c4 + 2][r] = v.z; As[c4 + 3][r] = v.w;
        }
#pragma unroll
        for (int it = 0; it < B_IT; it++) {
            int t = tid + it * THREADS;
            int kr = t / (BN / 4), nc = (t % (BN / 4)) * 4;
            float4 v = make_float4(0.f, 0.f, 0.f, 0.f);
            if (bn + nc < N) v = *(const float4*)(Bp + (size_t)(k0 + kr) * N + bn + nc);
            *(float4*)&Bs[kr][nc] = v;
        }
        __syncthreads();
#pragma unroll
        for (int kk = 0; kk < BK; kk++) {
            float a[TM], b[TN];
#pragma unroll
            for (int i = 0; i < TM; i++) a[i] = As[kk][ty * TM + i];
#pragma unroll
            for (int j = 0; j < TN; j++) b[j] = Bs[kk][tx * TN + j];
#pragma unroll
            for (int i = 0; i < TM; i++)
#pragma unroll
                for (int j = 0; j < TN; j++)
                    acc[i][j] = fmaf(a[i], b[j], acc[i][j]);
        }
        __syncthreads();
    }
    float* Cz = C + (size_t)z * M * N;
#pragma unroll
    for (int i = 0; i < TM; i++) {
        int m = bm + ty * TM + i;
        if (m >= M) continue;
#pragma unroll
        for (int j = 0; j < TN; j++) {
            int n = bn + tx * TN + j;
            if (n >= N) continue;
            Cz[(size_t)m * N + n] = acc[i][j];
        }
    }
}

// ---------------- orchestration ----------------
extern "C" void kernel_launch(void* const* d_in, const int* in_sizes, int n_in,
                              void* d_out, int out_size)
{
    using namespace cfg;
    const int*   tokens        = (const int*)  d_in[0];
    const float* embed         = (const float*)d_in[1];
    const float* ln1_g         = (const float*)d_in[2];
    const float* ln1_b         = (const float*)d_in[3];
    const float* cp_w1         = (const float*)d_in[4];
    const float* cp_b1         = (const float*)d_in[5];
    const float* cp_w2         = (const float*)d_in[6];
    const float* cp_b2         = (const float*)d_in[7];
    const float* pos_scale     = (const float*)d_in[8];
    const float* content_scale = (const float*)d_in[9];
    const float* val_w         = (const float*)d_in[10];
    const float* val_b         = (const float*)d_in[11];
    const float* oln_g         = (const float*)d_in[12];
    const float* oln_b         = (const float*)d_in[13];
    const float* out_w         = (const float*)d_in[14];
    const float* out_b         = (const float*)d_in[15];
    const float* ln2_g         = (const float*)d_in[16];
    const float* ln2_b         = (const float*)d_in[17];
    const float* ffn_w1        = (const float*)d_in[18];
    const float* ffn_b1        = (const float*)d_in[19];
    const float* ffn_w2        = (const float*)d_in[20];
    const float* ffn_b2        = (const float*)d_in[21];
    const float* no_g          = (const float*)d_in[22];
    const float* no_b          = (const float*)d_in[23];
    const float* head_b        = (const float*)d_in[24];
    float* out = (float*)d_out;

    float* base = nullptr;
    cudaGetSymbolAddress((void**)&base, g_scratch);
    float* h   = base + OFF_H;
    float* x   = base + OFF_X;
    float* t1  = base + OFF_T1;
    float* v   = base + OFF_V;
    float* ret = base + OFF_RET;
    float* r2  = base + OFF_R2;
    float* cp4 = base + OFF_CP4;
    float* cs  = base + OFF_CS;
    float* sc  = base + OFF_SC;
    float* f1  = base + OFF_F1;

    gather_k<<<(M * D / 4 + 255) / 256, 256>>>(tokens, embed, h, M, D);

    for (int i = 0; i < NL; i++) {
        ln_k<<<M, 256>>>(h, x, ln1_g + (size_t)i * D, ln1_b + (size_t)i * D, D);
        // t1 = tanh(x @ cp_w1 + b1)      [2048,512,512] -> mid 64x64, 256 blocks
        mm<0, ACT_TANH>(x, cp_w1 + (size_t)i * D * D, t1, M, D, D,
                        cp_b1 + (size_t)i * D, nullptr);
        // cp partials = t1 @ cp_w2 (split-K x4)   grid (1,64,4) = 256 blocks
        {
            dim3 g(K / 32, M / 32, 4);
            gemm_f32_splitk_k<32, 32, 32, 2, 2><<<g, 256>>>(
                t1, cp_w2 + (size_t)i * D * K, cp4, M, K, D, 4);
        }
        // v = x @ val_w + val_b
        mm<0, ACT_NONE>(x, val_w + (size_t)i * D * D, v, M, D, D,
                        val_b + (size_t)i * D, nullptr);
        // cs = [cos|sin] with fused split-K reduce + bias + pi*tanh
        phase_k<<<(B * L * K + 255) / 256, 256>>>(cp4, cp_b2 + (size_t)i * K, cs,
                                                  pos_scale, content_scale,
                                                  i, L, K, B * L * K);
        // scores = tril(P P^T)  [L,L,64] x2 -> mid 64x64, 512 blocks
        mm<1, ACT_NONE>(cs, cs, sc, L, L, CS, nullptr, nullptr, nullptr,
                        /*causal=*/1, 0, 0.f,
                        /*gz=*/B, (long)L * CS, (long)L * CS, (long)L * L);
        // ret = (scores @ v) * rsqrt((m+1)*K)  [L,D,L] x2 -> mid, 256 blocks
        mm<0, ACT_NONE>(sc, v, ret, L, D, L, nullptr, nullptr, nullptr,
                        0, /*rowscale=*/1, (float)K,
                        /*gz=*/B, (long)L * L, (long)L * D, (long)L * D);
        ln_k<<<M, 256>>>(ret, r2, oln_g + (size_t)i * D, oln_b + (size_t)i * D, D);
        // h = (h + x) + r2 @ out_w + out_b    (dual residual)
        mm<0, ACT_NONE>(r2, out_w + (size_t)i * D * D, h, M, D, D,
                        out_b + (size_t)i * D, h, x);
        ln_k<<<M, 256>>>(h, x, ln2_g + (size_t)i * D, ln2_b + (size_t)i * D, D);
        // f1 = gelu(x @ ffn_w1 + b1)   [2048,2048,512] -> big tiles, 256 blocks
        mm<0, ACT_GELU>(x, ffn_w1 + (size_t)i * D * FF, f1, M, FF, D,
                        ffn_b1 + (size_t)i * FF, nullptr);
        // h = h + f1 @ ffn_w2 + b2     [2048,512,2048] -> mid tiles
        mm<0, ACT_NONE>(f1, ffn_w2 + (size_t)i * FF * D, h, M, D, FF,
                        ffn_b2 + (size_t)i * D, h);
    }

    ln_k<<<M, 256>>>(h, x, no_g, no_b, D);
    // logits = LN(h) @ embed^T + head_b   [2048,32000,512] -> big tiles
    mm<1, ACT_NONE>(x, embed, out, M, V, D, head_b, nullptr);
}

// round 16
// speedup vs baseline: 1.1603x; 1.0336x over previous
#include <cuda_runtime.h>
#include <cstdint>
#include <math.h>

// ============================================================================
// UnifiedDualPhasorLM — mma.sync tf32 tensor-core GEMMs (sm_80+ path).
//   retrieval rewritten as causal attention: scores = tril(P P^T), P=[cos|sin]
//   R16: + causal K-truncation in ret GEMM (upper-tri chunks are exact zeros),
//        + vectorized 128-thread ln_k. Base = R15 (1834 us PASS).
// ============================================================================

namespace cfg {
constexpr int B = 2, L = 1024, D = 512, K = 32, NL = 4, FF = 2048, V = 32000;
constexpr int M = B * L;      // 2048
constexpr int CS = 2 * K;     // 64
}

// ---------------- scratch ----------------
constexpr size_t SZ_MD  = (size_t)cfg::M * cfg::D;
constexpr size_t OFF_H   = 0;
constexpr size_t OFF_X   = OFF_H   + SZ_MD;
constexpr size_t OFF_T1  = OFF_X   + SZ_MD;
constexpr size_t OFF_V   = OFF_T1  + SZ_MD;
constexpr size_t OFF_RET = OFF_V   + SZ_MD;
constexpr size_t OFF_R2  = OFF_RET + SZ_MD;
constexpr size_t OFF_CP4 = OFF_R2  + SZ_MD;                          // 4 split-K planes
constexpr size_t OFF_CS  = OFF_CP4 + 4 * (size_t)cfg::M * cfg::K;
constexpr size_t OFF_SC  = OFF_CS  + (size_t)cfg::M * cfg::CS;       // 2 planes [L,L]
constexpr size_t OFF_F1  = OFF_SC  + 2 * (size_t)cfg::L * cfg::L;
constexpr size_t SCRATCH_FLOATS = OFF_F1 + (size_t)cfg::M * cfg::FF;

__device__ float g_scratch[SCRATCH_FLOATS];

// ---------------- tf32 helpers ----------------
__device__ __forceinline__ float to_tf32(float x) {
    uint32_t u;
    asm("cvt.rna.tf32.f32 %0, %1;" : "=r"(u) : "f"(x));
    return __uint_as_float(u);
}
__device__ __forceinline__ void mma1688(float* d, const uint32_t* a, const uint32_t* b) {
    asm volatile(
        "mma.sync.aligned.m16n8k8.row.col.f32.tf32.tf32.f32 "
        "{%0,%1,%2,%3}, {%4,%5,%6,%7}, {%8,%9}, {%0,%1,%2,%3};"
        : "+f"(d[0]), "+f"(d[1]), "+f"(d[2]), "+f"(d[3])
        : "r"(a[0]), "r"(a[1]), "r"(a[2]), "r"(a[3]), "r"(b[0]), "r"(b[1]));
}

// ================== tf32 mma.sync GEMM, tile-size templated =================
// C[M,N] = act(A[M,Kd] @ op(B) + bias) (*causal)(*rowscale)(+resid)(+resid2)
// TRANSB=1: B is [N,Kd] row-major. TRANSB=0: B is [Kd,N] row-major.
// ktrunc: A columns >= bm+BM are known-zero (causal scores) -> truncate K loop.
// Requires M%BM==0, N%BN==0, Kd%32==0 at call sites.
constexpr int SROW = 36;

template<int BM, int BN, int WM, int WN, int TRANSB, int ACT>
__global__ void __launch_bounds__(32 * (BM / WM) * (BN / WN))
mma_gemm_k(const float* __restrict__ A, const float* __restrict__ Bp,
           float* __restrict__ C, int M, int N, int Kd,
           const float* __restrict__ bias, const float* __restrict__ resid,
           const float* __restrict__ resid2,
           int causal, int rowscale, float kf, int ktrunc,
           long sAz, long sBz, long sCz)
{
    constexpr int WARPS_M = BM / WM;
    constexpr int THREADS = 32 * WARPS_M * (BN / WN);
    constexpr int MF = WM / 16;
    constexpr int NF = WN / 8;
    constexpr int TILE_FA = BM * SROW;
    constexpr int TILE_FB = BN * SROW;
    constexpr int A_IT = BM * 32 / (4 * THREADS);
    constexpr int B_IT = BN * 32 / (4 * THREADS);
    constexpr int KGRP = THREADS / BN;          // groups for TRANSB=0 ldg
    constexpr int KPG  = 32 / KGRP;             // k per group
    constexpr int Z_IT = BM * BN / (4 * THREADS);

    extern __shared__ float smf[];
    float* sA = smf;                   // [2][BM][SROW]
    float* sB = smf + 2 * TILE_FA;     // [2][BN][SROW]

    A  += (size_t)blockIdx.z * sAz;
    Bp += (size_t)blockIdx.z * sBz;
    C  += (size_t)blockIdx.z * sCz;
    if (resid)  resid  += (size_t)blockIdx.z * sCz;
    if (resid2) resid2 += (size_t)blockIdx.z * sCz;

    const int tid  = threadIdx.x;
    const int lane = tid & 31;
    const int wid  = tid >> 5;
    const int wm   = wid % WARPS_M;
    const int wn   = wid / WARPS_M;
    const int gl   = lane >> 2;      // groupID (0..7)
    const int tl   = lane & 3;       // thread in group (0..3)
    const int bm = blockIdx.y * BM;
    const int bn = blockIdx.x * BN;

    // fully-masked causal tile -> zeros
    if (causal && bn > bm + BM - 1) {
#pragma unroll
        for (int it = 0; it < Z_IT; it++) {
            int idx = tid + it * THREADS;
            int m = idx / (BN / 4), nc = (idx % (BN / 4)) * 4;
            *(float4*)(C + (size_t)(bm + m) * N + bn + nc) = make_float4(0.f, 0.f, 0.f, 0.f);
        }
        return;
    }

    float4 ra[A_IT];
    float4 rb4[B_IT];        // TRANSB=1 staging
    float  rbk[KPG];         // TRANSB=0 staging

    auto ldgA = [&](int k0) {
#pragma unroll
        for (int it = 0; it < A_IT; it++) {
            int idx = tid + it * THREADS;
            float4 v = *(const float4*)(A + (size_t)(bm + (idx >> 3)) * Kd + k0 + (idx & 7) * 4);
            v.x = to_tf32(v.x); v.y = to_tf32(v.y); v.z = to_tf32(v.z); v.w = to_tf32(v.w);
            ra[it] = v;
        }
    };
    auto stsA = [&](int s) {
        float* dst = sA + s * TILE_FA;
#pragma unroll
        for (int it = 0; it < A_IT; it++) {
            int idx = tid + it * THREADS;
            *(float4*)(dst + (idx >> 3) * SROW + (idx & 7) * 4) = ra[it];
        }
    };
    auto ldgB = [&](int k0) {
        if (TRANSB) {
#pragma unroll
            for (int it = 0; it < B_IT; it++) {
                int idx = tid + it * THREADS;
                float4 v = *(const float4*)(Bp + (size_t)(bn + (idx >> 3)) * Kd + k0 + (idx & 7) * 4);
                v.x = to_tf32(v.x); v.y = to_tf32(v.y); v.z = to_tf32(v.z); v.w = to_tf32(v.w);
                rb4[it] = v;
            }
        } else {
            int n = tid % BN, kh = (tid / BN) * KPG;
#pragma unroll
            for (int j = 0; j < KPG; j++)
                rbk[j] = to_tf32(Bp[(size_t)(k0 + kh + j) * N + bn + n]);
        }
    };
    auto stsB = [&](int s) {
        float* dst = sB + s * TILE_FB;
        if (TRANSB) {
#pragma unroll
            for (int it = 0; it < B_IT; it++) {
                int idx = tid + it * THREADS;
                *(float4*)(dst + (idx >> 3) * SROW + (idx & 7) * 4) = rb4[it];
            }
        } else {
            int n = tid % BN, kh = (tid / BN) * KPG;
#pragma unroll
            for (int g = 0; g < KPG / 4; g++)
                *(float4*)(dst + n * SROW + kh + g * 4) =
                    make_float4(rbk[4*g], rbk[4*g+1], rbk[4*g+2], rbk[4*g+3]);
        }
    };

    float acc[MF][NF][4];
#pragma unroll
    for (int i = 0; i < MF; i++)
#pragma unroll
        for (int j = 0; j < NF; j++)
#pragma unroll
            for (int r = 0; r < 4; r++) acc[i][j][r] = 0.f;

    const int CHUNKS = Kd >> 5;
    // causal K-truncation: A[:, k] == 0 for k >= bm+BM (exact zeros from the
    // scores kernel), so those chunks contribute nothing.
    const int CH = ktrunc ? min(CHUNKS, (bm + BM + 31) >> 5) : CHUNKS;

    // prologue
    ldgA(0); ldgB(0);
    stsA(0); stsB(0);
    __syncthreads();

    int buf = 0;
    for (int c = 0; c < CH; c++) {
        const bool more = (c + 1 < CH);
        if (more) { ldgA((c + 1) << 5); ldgB((c + 1) << 5); }

        const float* cA = sA + buf * TILE_FA;
        const float* cB = sB + buf * TILE_FB;
#pragma unroll
        for (int ks = 0; ks < 4; ks++) {
            const int kk = ks * 8 + tl;
            uint32_t av[MF][4], bv[NF][2];
#pragma unroll
            for (int mf = 0; mf < MF; mf++) {
                int mr = wm * WM + mf * 16 + gl;
                av[mf][0] = __float_as_uint(cA[ mr      * SROW + kk    ]);
                av[mf][1] = __float_as_uint(cA[(mr + 8) * SROW + kk    ]);
                av[mf][2] = __float_as_uint(cA[ mr      * SROW + kk + 4]);
                av[mf][3] = __float_as_uint(cA[(mr + 8) * SROW + kk + 4]);
            }
#pragma unroll
            for (int nf = 0; nf < NF; nf++) {
                int nr = wn * WN + nf * 8 + gl;
                bv[nf][0] = __float_as_uint(cB[nr * SROW + kk    ]);
                bv[nf][1] = __float_as_uint(cB[nr * SROW + kk + 4]);
            }
#pragma unroll
            for (int mf = 0; mf < MF; mf++)
#pragma unroll
                for (int nf = 0; nf < NF; nf++)
                    mma1688(acc[mf][nf], av[mf], bv[nf]);
        }

        if (more) {
            stsA(buf ^ 1); stsB(buf ^ 1);
            __syncthreads();
            buf ^= 1;
        }
    }

    // epilogue: c0=(g,2t) c1=(g,2t+1) c2=(g+8,2t) c3=(g+8,2t+1)
#pragma unroll
    for (int mf = 0; mf < MF; mf++)
#pragma unroll
        for (int nf = 0; nf < NF; nf++) {
            int m0 = bm + wm * WM + mf * 16 + gl;
            int n0 = bn + wn * WN + nf * 8 + tl * 2;
            float b0 = 0.f, b1 = 0.f;
            if (bias) { b0 = __ldg(bias + n0); b1 = __ldg(bias + n0 + 1); }
#pragma unroll
            for (int rr = 0; rr < 2; rr++) {
                int m = m0 + rr * 8;
                float v0 = acc[mf][nf][rr * 2 + 0] + b0;
                float v1 = acc[mf][nf][rr * 2 + 1] + b1;
                if (ACT == 1)      { v0 = tanhf(v0); v1 = tanhf(v1); }
                else if (ACT == 2) {
                    v0 = 0.5f * v0 * (1.f + erff(v0 * 0.7071067811865476f));
                    v1 = 0.5f * v1 * (1.f + erff(v1 * 0.7071067811865476f));
                }
                if (causal) { if (n0 > m) v0 = 0.f; if (n0 + 1 > m) v1 = 0.f; }
                if (rowscale) {
                    float rs = rsqrtf((float)(m + 1) * kf);
                    v0 *= rs; v1 *= rs;
                }
                if (resid) {
                    float2 rv = *(const float2*)(resid + (size_t)m * N + n0);
                    v0 += rv.x; v1 += rv.y;
                }
                if (resid2) {
                    float2 rv = *(const float2*)(resid2 + (size_t)m * N + n0);
                    v0 += rv.x; v1 += rv.y;
                }
                *(float2*)(C + (size_t)m * N + n0) = make_float2(v0, v1);
            }
        }
}

enum { ACT_NONE = 0, ACT_TANH = 1, ACT_GELU = 2, ACT_TANHPI = 3 };

// big: 128x128 tiles, 8 warps; mid: 64x64 tiles, 4 warps (R8 config)
template<int TRANSB, int ACT>
static void mm(const float* A, const float* Bp, float* C, int M, int N, int Kd,
               const float* bias, const float* resid, const float* resid2 = nullptr,
               int causal = 0, int rowscale = 0, float kf = 32.f,
               int gz = 1, long sAz = 0, long sBz = 0, long sCz = 0,
               int ktrunc = 0)
{
    long big_blocks = (long)(M / 128) * (N / 128) * gz;
    if (N % 128 == 0 && big_blocks >= 148) {
        constexpr int SM_BYTES = 2 * (128 + 128) * SROW * 4;   // 73728
        cudaFuncSetAttribute(mma_gemm_k<128, 128, 32, 64, TRANSB, ACT>,
                             cudaFuncAttributeMaxDynamicSharedMemorySize, SM_BYTES);
        dim3 g(N / 128, M / 128, gz);
        mma_gemm_k<128, 128, 32, 64, TRANSB, ACT><<<g, 256, SM_BYTES>>>(
            A, Bp, C, M, N, Kd, bias, resid, resid2, causal, rowscale, kf, ktrunc,
            sAz, sBz, sCz);
    } else {
        constexpr int SM_BYTES = 2 * (64 + 64) * SROW * 4;     // 36864
        dim3 g(N / 64, M / 64, gz);
        mma_gemm_k<64, 64, 32, 32, TRANSB, ACT><<<g, 128, SM_BYTES>>>(
            A, Bp, C, M, N, Kd, bias, resid, resid2, causal, rowscale, kf, ktrunc,
            sAz, sBz, sCz);
    }
}

// ================== small helpers ================================
__device__ __forceinline__ float block_sum(float v, float* red) {
    int lane = threadIdx.x & 31, w = threadIdx.x >> 5;
#pragma unroll
    for (int o = 16; o; o >>= 1) v += __shfl_xor_sync(0xffffffffu, v, o);
    __syncthreads();
    if (lane == 0) red[w] = v;
    __syncthreads();
    float t = (threadIdx.x < (blockDim.x >> 5)) ? red[threadIdx.x] : 0.f;
    if (w == 0) {
#pragma unroll
        for (int o = 16; o; o >>= 1) t += __shfl_xor_sync(0xffffffffu, t, o);
        if (lane == 0) red[32] = t;
    }
    __syncthreads();
    return red[32];
}

// vectorized LayerNorm: Dn == 4*blockDim.x (D=512, 128 threads)
__global__ void ln_k(const float* __restrict__ X, float* __restrict__ Y,
                     const float* __restrict__ g, const float* __restrict__ b, int Dn)
{
    __shared__ float red[33];
    int row = blockIdx.x;
    float4 v = ((const float4*)(X + (size_t)row * Dn))[threadIdx.x];
    float s = v.x + v.y + v.z + v.w;
    float mean = block_sum(s, red) / (float)Dn;
    float dx = v.x - mean, dy = v.y - mean, dz = v.z - mean, dw = v.w - mean;
    float q = dx * dx + dy * dy + dz * dz + dw * dw;
    float var = block_sum(q, red) / (float)Dn;
    float inv = rsqrtf(var + 1e-5f);
    float4 g4 = ((const float4*)g)[threadIdx.x];
    float4 b4 = ((const float4*)b)[threadIdx.x];
    float4 o;
    o.x = dx * inv * g4.x + b4.x;
    o.y = dy * inv * g4.y + b4.y;
    o.z = dz * inv * g4.z + b4.z;
    o.w = dw * inv * g4.w + b4.w;
    ((float4*)(Y + (size_t)row * Dn))[threadIdx.x] = o;
}

__global__ void gather_k(const int* __restrict__ tok, const float* __restrict__ emb,
                         float* __restrict__ h, int n, int Dn)
{
    int i = blockIdx.x * blockDim.x + threadIdx.x;
    int total = n * (Dn / 4);
    if (i >= total) return;
    int row = i / (Dn / 4), c = i % (Dn / 4);
    ((float4*)h)[i] = ((const float4*)(emb + (size_t)tok[row] * Dn))[c];
}

// phase_k with fused split-K reduction + bias + pi*tanh:
// cp_raw = sum_z cp4[z*MK + i] + b2[k];  cp = pi*tanh(cp_raw)
__global__ void phase_k(const float* __restrict__ cp4, const float* __restrict__ b2,
                        float* __restrict__ cs,
                        const float* __restrict__ ps_arr, const float* __restrict__ cs_arr,
                        int layer, int Ln, int Kn, int total)
{
    int i = blockIdx.x * blockDim.x + threadIdx.x;
    if (i >= total) return;
    int k  = i % Kn;
    int l  = (i / Kn) % Ln;
    int bl = i / Kn;
    float s = cp4[i] + cp4[total + i] + cp4[2 * total + i] + cp4[3 * total + i] + b2[k];
    float cpv = 3.14159274101257324f * tanhf(s);
    float freq = (float)exp(-(double)k / (double)Kn * 9.210340371976184);
    float pos  = __fmul_rn((float)l, freq);
    float tp   = __fadd_rn(__fmul_rn(ps_arr[layer], pos),
                           __fmul_rn(cs_arr[layer], cpv));
    float* o = cs + (size_t)bl * (2 * Kn);
    o[k]      = cosf(tp);
    o[Kn + k] = sinf(tp);
}

// ---- fp32 split-K GEMM for cp_w2 (N=32): raw partials, 4-way K split ----
template<int BM, int BN, int BK, int TM, int TN>
__global__ void gemm_f32_splitk_k(const float* __restrict__ A, const float* __restrict__ Bp,
                                  float* __restrict__ C, int M, int N, int Kd, int split)
{
    constexpr int THREADS = (BM / TM) * (BN / TN);
    __shared__ float As[BK][BM + 4];
    __shared__ float Bs[BK][BN + 4];
    const int tid = threadIdx.x;
    const int bm = blockIdx.y * BM, bn = blockIdx.x * BN;
    const int z  = blockIdx.z;
    const int kslice = Kd / split;
    const int kbeg = z * kslice, kend = kbeg + kslice;
    const int tx = tid % (BN / TN), ty = tid / (BN / TN);

    float acc[TM][TN];
#pragma unroll
    for (int i = 0; i < TM; i++)
#pragma unroll
        for (int j = 0; j < TN; j++) acc[i][j] = 0.f;

    constexpr int A_IT = (BM * BK) / (4 * THREADS);
    constexpr int B_IT = (BK * BN) / (4 * THREADS);

    for (int k0 = kbeg; k0 < kend; k0 += BK) {
#pragma unroll
        for (int it = 0; it < A_IT; it++) {
            int t = tid + it * THREADS;
            int r = t / (BK / 4), c4 = (t % (BK / 4)) * 4;
            int m = bm + r;
            float4 v = make_float4(0.f, 0.f, 0.f, 0.f);
            if (m < M) v = *(const float4*)(A + (size_t)m * Kd + k0 + c4);
            As[c4 + 0][r] = v.x; As[c4 + 1][r] = v.y;
            As[c4 + 2][r] = v.z; As[c4 + 3][r] = v.w;
        }
#pragma unroll
        for (int it = 0; it < B_IT; it++) {
            int t = tid + it * THREADS;
            int kr = t / (BN / 4), nc = (t % (BN / 4)) * 4;
            float4 v = make_float4(0.f, 0.f, 0.f, 0.f);
            if (bn + nc < N) v = *(const float4*)(Bp + (size_t)(k0 + kr) * N + bn + nc);
            *(float4*)&Bs[kr][nc] = v;
        }
        __syncthreads();
#pragma unroll
        for (int kk = 0; kk < BK; kk++) {
            float a[TM], b[TN];
#pragma unroll
            for (int i = 0; i < TM; i++) a[i] = As[kk][ty * TM + i];
#pragma unroll
            for (int j = 0; j < TN; j++) b[j] = Bs[kk][tx * TN + j];
#pragma unroll
            for (int i = 0; i < TM; i++)
#pragma unroll
                for (int j = 0; j < TN; j++)
                    acc[i][j] = fmaf(a[i], b[j], acc[i][j]);
        }
        __syncthreads();
    }
    float* Cz = C + (size_t)z * M * N;
#pragma unroll
    for (int i = 0; i < TM; i++) {
        int m = bm + ty * TM + i;
        if (m >= M) continue;
#pragma unroll
        for (int j = 0; j < TN; j++) {
            int n = bn + tx * TN + j;
            if (n >= N) continue;
            Cz[(size_t)m * N + n] = acc[i][j];
        }
    }
}

// ---------------- orchestration ----------------
extern "C" void kernel_launch(void* const* d_in, const int* in_sizes, int n_in,
                              void* d_out, int out_size)
{
    using namespace cfg;
    const int*   tokens        = (const int*)  d_in[0];
    const float* embed         = (const float*)d_in[1];
    const float* ln1_g         = (const float*)d_in[2];
    const float* ln1_b         = (const float*)d_in[3];
    const float* cp_w1         = (const float*)d_in[4];
    const float* cp_b1         = (const float*)d_in[5];
    const float* cp_w2         = (const float*)d_in[6];
    const float* cp_b2         = (const float*)d_in[7];
    const float* pos_scale     = (const float*)d_in[8];
    const float* content_scale = (const float*)d_in[9];
    const float* val_w         = (const float*)d_in[10];
    const float* val_b         = (const float*)d_in[11];
    const float* oln_g         = (const float*)d_in[12];
    const float* oln_b         = (const float*)d_in[13];
    const float* out_w         = (const float*)d_in[14];
    const float* out_b         = (const float*)d_in[15];
    const float* ln2_g         = (const float*)d_in[16];
    const float* ln2_b         = (const float*)d_in[17];
    const float* ffn_w1        = (const float*)d_in[18];
    const float* ffn_b1        = (const float*)d_in[19];
    const float* ffn_w2        = (const float*)d_in[20];
    const float* ffn_b2        = (const float*)d_in[21];
    const float* no_g          = (const float*)d_in[22];
    const float* no_b          = (const float*)d_in[23];
    const float* head_b        = (const float*)d_in[24];
    float* out = (float*)d_out;

    float* base = nullptr;
    cudaGetSymbolAddress((void**)&base, g_scratch);
    float* h   = base + OFF_H;
    float* x   = base + OFF_X;
    float* t1  = base + OFF_T1;
    float* v   = base + OFF_V;
    float* ret = base + OFF_RET;
    float* r2  = base + OFF_R2;
    float* cp4 = base + OFF_CP4;
    float* cs  = base + OFF_CS;
    float* sc  = base + OFF_SC;
    float* f1  = base + OFF_F1;

    gather_k<<<(M * D / 4 + 255) / 256, 256>>>(tokens, embed, h, M, D);

    for (int i = 0; i < NL; i++) {
        ln_k<<<M, 128>>>(h, x, ln1_g + (size_t)i * D, ln1_b + (size_t)i * D, D);
        // t1 = tanh(x @ cp_w1 + b1)      [2048,512,512] -> mid 64x64, 256 blocks
        mm<0, ACT_TANH>(x, cp_w1 + (size_t)i * D * D, t1, M, D, D,
                        cp_b1 + (size_t)i * D, nullptr);
        // cp partials = t1 @ cp_w2 (split-K x4)   grid (1,64,4) = 256 blocks
        {
            dim3 g(K / 32, M / 32, 4);
            gemm_f32_splitk_k<32, 32, 32, 2, 2><<<g, 256>>>(
                t1, cp_w2 + (size_t)i * D * K, cp4, M, K, D, 4);
        }
        // v = x @ val_w + val_b
        mm<0, ACT_NONE>(x, val_w + (size_t)i * D * D, v, M, D, D,
                        val_b + (size_t)i * D, nullptr);
        // cs = [cos|sin] with fused split-K reduce + bias + pi*tanh
        phase_k<<<(B * L * K + 255) / 256, 256>>>(cp4, cp_b2 + (size_t)i * K, cs,
                                                  pos_scale, content_scale,
                                                  i, L, K, B * L * K);
        // scores = tril(P P^T)  [L,L,64] x2 -> mid 64x64, 512 blocks
        mm<1, ACT_NONE>(cs, cs, sc, L, L, CS, nullptr, nullptr, nullptr,
                        /*causal=*/1, 0, 0.f,
                        /*gz=*/B, (long)L * CS, (long)L * CS, (long)L * L);
        // ret = (scores @ v) * rsqrt((m+1)*K)  [L,D,L] x2 -> mid, 256 blocks
        // ktrunc: sc upper triangle is exact zero -> truncate K loop per row-block
        mm<0, ACT_NONE>(sc, v, ret, L, D, L, nullptr, nullptr, nullptr,
                        0, /*rowscale=*/1, (float)K,
                        /*gz=*/B, (long)L * L, (long)L * D, (long)L * D,
                        /*ktrunc=*/1);
        ln_k<<<M, 128>>>(ret, r2, oln_g + (size_t)i * D, oln_b + (size_t)i * D, D);
        // h = (h + x) + r2 @ out_w + out_b    (dual residual)
        mm<0, ACT_NONE>(r2, out_w + (size_t)i * D * D, h, M, D, D,
                        out_b + (size_t)i * D, h, x);
        ln_k<<<M, 128>>>(h, x, ln2_g + (size_t)i * D, ln2_b + (size_t)i * D, D);
        // f1 = gelu(x @ ffn_w1 + b1)   [2048,2048,512] -> big tiles, 256 blocks
        mm<0, ACT_GELU>(x, ffn_w1 + (size_t)i * D * FF, f1, M, FF, D,
                        ffn_b1 + (size_t)i * FF, nullptr);
        // h = h + f1 @ ffn_w2 + b2     [2048,512,2048] -> mid tiles
        mm<0, ACT_NONE>(f1, ffn_w2 + (size_t)i * FF * D, h, M, D, FF,
                        ffn_b2 + (size_t)i * D, h);
    }

    ln_k<<<M, 128>>>(h, x, no_g, no_b, D);
    // logits = LN(h) @ embed^T + head_b   [2048,32000,512] -> big tiles
    mm<1, ACT_NONE>(x, embed, out, M, V, D, head_b, nullptr);
}

// round 17
// speedup vs baseline: 1.5359x; 1.3237x over previous
#include <cuda_runtime.h>
#include <cuda_fp16.h>
#include <cstdint>
#include <math.h>

// ============================================================================
// UnifiedDualPhasorLM — fp16-operand mma.sync (m16n8k16, fp32 accumulate).
//   fp16 mantissa == tf32 mantissa (10 bits) -> same operand rounding as the
//   validated tf32 path; range verified <= 64 across all call sites.
//   retrieval rewritten as causal attention: scores = tril(P P^T), P=[cos|sin]
//   R17 = R16 (1774 us PASS) with the GEMM operand path switched to fp16:
//   half the k-steps, half the LDS/HMMA instructions, half the SMEM.
// ============================================================================

namespace cfg {
constexpr int B = 2, L = 1024, D = 512, K = 32, NL = 4, FF = 2048, V = 32000;
constexpr int M = B * L;      // 2048
constexpr int CS = 2 * K;     // 64
}

// ---------------- scratch ----------------
constexpr size_t SZ_MD  = (size_t)cfg::M * cfg::D;
constexpr size_t OFF_H   = 0;
constexpr size_t OFF_X   = OFF_H   + SZ_MD;
constexpr size_t OFF_T1  = OFF_X   + SZ_MD;
constexpr size_t OFF_V   = OFF_T1  + SZ_MD;
constexpr size_t OFF_RET = OFF_V   + SZ_MD;
constexpr size_t OFF_R2  = OFF_RET + SZ_MD;
constexpr size_t OFF_CP4 = OFF_R2  + SZ_MD;                          // 4 split-K planes
constexpr size_t OFF_CS  = OFF_CP4 + 4 * (size_t)cfg::M * cfg::K;
constexpr size_t OFF_SC  = OFF_CS  + (size_t)cfg::M * cfg::CS;       // 2 planes [L,L]
constexpr size_t OFF_F1  = OFF_SC  + 2 * (size_t)cfg::L * cfg::L;
constexpr size_t SCRATCH_FLOATS = OFF_F1 + (size_t)cfg::M * cfg::FF;

__device__ float g_scratch[SCRATCH_FLOATS];

// ---------------- fp16 helpers ----------------
__device__ __forceinline__ uint32_t pack2(float a, float b) {
    __half2 h = __floats2half2_rn(a, b);
    return *(uint32_t*)&h;
}
__device__ __forceinline__ void mma16816(float* d, const uint32_t* a, const uint32_t* b) {
    asm volatile(
        "mma.sync.aligned.m16n8k16.row.col.f32.f16.f16.f32 "
        "{%0,%1,%2,%3}, {%4,%5,%6,%7}, {%8,%9}, {%0,%1,%2,%3};"
        : "+f"(d[0]), "+f"(d[1]), "+f"(d[2]), "+f"(d[3])
        : "r"(a[0]), "r"(a[1]), "r"(a[2]), "r"(a[3]), "r"(b[0]), "r"(b[1]));
}

// ================== fp16 mma.sync GEMM, tile-size templated =================
// C[M,N] = act(A[M,Kd] @ op(B) + bias) (*causal)(*rowscale)(+resid)(+resid2)
// TRANSB=1: B is [N,Kd] row-major. TRANSB=0: B is [Kd,N] row-major.
// ktrunc: A columns >= bm+BM are known-zero (causal scores) -> truncate K loop.
// SMEM rows are 32 halves padded to SROWH=40 (20 words): fragment LDS bank =
// (gl*20 + ks*8 + tl) mod 32 = full permutation -> conflict-free.
constexpr int SROWH = 40;

template<int BM, int BN, int WM, int WN, int TRANSB, int ACT>
__global__ void __launch_bounds__(32 * (BM / WM) * (BN / WN))
mma_gemm_k(const float* __restrict__ A, const float* __restrict__ Bp,
           float* __restrict__ C, int M, int N, int Kd,
           const float* __restrict__ bias, const float* __restrict__ resid,
           const float* __restrict__ resid2,
           int causal, int rowscale, float kf, int ktrunc,
           long sAz, long sBz, long sCz)
{
    constexpr int WARPS_M = BM / WM;
    constexpr int THREADS = 32 * WARPS_M * (BN / WN);
    constexpr int MF = WM / 16;
    constexpr int NF = WN / 8;
    constexpr int TILE_HA = BM * SROWH;          // halves
    constexpr int TILE_HB = BN * SROWH;
    constexpr int A_IT = BM * 32 / (4 * THREADS);
    constexpr int B_IT = BN * 32 / (4 * THREADS);
    constexpr int KGRP = THREADS / BN;           // groups for TRANSB=0 ldg
    constexpr int KPG  = 32 / KGRP;              // k per group
    constexpr int Z_IT = BM * BN / (4 * THREADS);

    extern __shared__ __half smh[];
    __half* sA = smh;                    // [2][BM][SROWH]
    __half* sB = smh + 2 * TILE_HA;      // [2][BN][SROWH]

    A  += (size_t)blockIdx.z * sAz;
    Bp += (size_t)blockIdx.z * sBz;
    C  += (size_t)blockIdx.z * sCz;
    if (resid)  resid  += (size_t)blockIdx.z * sCz;
    if (resid2) resid2 += (size_t)blockIdx.z * sCz;

    const int tid  = threadIdx.x;
    const int lane = tid & 31;
    const int wid  = tid >> 5;
    const int wm   = wid % WARPS_M;
    const int wn   = wid / WARPS_M;
    const int gl   = lane >> 2;      // groupID (0..7)
    const int tl   = lane & 3;       // thread in group (0..3)
    const int bm = blockIdx.y * BM;
    const int bn = blockIdx.x * BN;

    // fully-masked causal tile -> zeros
    if (causal && bn > bm + BM - 1) {
#pragma unroll
        for (int it = 0; it < Z_IT; it++) {
            int idx = tid + it * THREADS;
            int m = idx / (BN / 4), nc = (idx % (BN / 4)) * 4;
            *(float4*)(C + (size_t)(bm + m) * N + bn + nc) = make_float4(0.f, 0.f, 0.f, 0.f);
        }
        return;
    }

    uint2 ra[A_IT];
    uint2 rb4[B_IT];         // TRANSB=1 staging (packed halves)
    float rbk[KPG];          // TRANSB=0 staging

    auto ldgA = [&](int k0) {
#pragma unroll
        for (int it = 0; it < A_IT; it++) {
            int idx = tid + it * THREADS;
            float4 v = *(const float4*)(A + (size_t)(bm + (idx >> 3)) * Kd + k0 + (idx & 7) * 4);
            ra[it] = make_uint2(pack2(v.x, v.y), pack2(v.z, v.w));
        }
    };
    auto stsA = [&](int s) {
        __half* dst = sA + s * TILE_HA;
#pragma unroll
        for (int it = 0; it < A_IT; it++) {
            int idx = tid + it * THREADS;
            *(uint2*)(dst + (idx >> 3) * SROWH + (idx & 7) * 4) = ra[it];
        }
    };
    auto ldgB = [&](int k0) {
        if (TRANSB) {
#pragma unroll
            for (int it = 0; it < B_IT; it++) {
                int idx = tid + it * THREADS;
                float4 v = *(const float4*)(Bp + (size_t)(bn + (idx >> 3)) * Kd + k0 + (idx & 7) * 4);
                rb4[it] = make_uint2(pack2(v.x, v.y), pack2(v.z, v.w));
            }
        } else {
            int n = tid % BN, kh = (tid / BN) * KPG;
#pragma unroll
            for (int j = 0; j < KPG; j++)
                rbk[j] = Bp[(size_t)(k0 + kh + j) * N + bn + n];
        }
    };
    auto stsB = [&](int s) {
        __half* dst = sB + s * TILE_HB;
        if (TRANSB) {
#pragma unroll
            for (int it = 0; it < B_IT; it++) {
                int idx = tid + it * THREADS;
                *(uint2*)(dst + (idx >> 3) * SROWH + (idx & 7) * 4) = rb4[it];
            }
        } else {
            int n = tid % BN, kh = (tid / BN) * KPG;
#pragma unroll
            for (int g = 0; g < KPG / 4; g++)
                *(uint2*)(dst + n * SROWH + kh + g * 4) =
                    make_uint2(pack2(rbk[4*g], rbk[4*g+1]), pack2(rbk[4*g+2], rbk[4*g+3]));
        }
    };

    float acc[MF][NF][4];
#pragma unroll
    for (int i = 0; i < MF; i++)
#pragma unroll
        for (int j = 0; j < NF; j++)
#pragma unroll
            for (int r = 0; r < 4; r++) acc[i][j][r] = 0.f;

    const int CHUNKS = Kd >> 5;
    // causal K-truncation: A[:, k] == 0 for k >= bm+BM (exact zeros).
    const int CH = ktrunc ? min(CHUNKS, (bm + BM + 31) >> 5) : CHUNKS;

    // prologue
    ldgA(0); ldgB(0);
    stsA(0); stsB(0);
    __syncthreads();

    int buf = 0;
    for (int c = 0; c < CH; c++) {
        const bool more = (c + 1 < CH);
        if (more) { ldgA((c + 1) << 5); ldgB((c + 1) << 5); }

        const __half* cA = sA + buf * TILE_HA;
        const __half* cB = sB + buf * TILE_HB;
#pragma unroll
        for (int ks = 0; ks < 2; ks++) {          // 2 x k16 per 32-k chunk
            const int kh = ks * 16 + tl * 2;      // half offset
            uint32_t av[MF][4], bv[NF][2];
#pragma unroll
            for (int mf = 0; mf < MF; mf++) {
                int mr = wm * WM + mf * 16 + gl;
                av[mf][0] = *(const uint32_t*)(cA +  mr      * SROWH + kh);
                av[mf][1] = *(const uint32_t*)(cA + (mr + 8) * SROWH + kh);
                av[mf][2] = *(const uint32_t*)(cA +  mr      * SROWH + kh + 8);
                av[mf][3] = *(const uint32_t*)(cA + (mr + 8) * SROWH + kh + 8);
            }
#pragma unroll
            for (int nf = 0; nf < NF; nf++) {
                int nr = wn * WN + nf * 8 + gl;
                bv[nf][0] = *(const uint32_t*)(cB + nr * SROWH + kh);
                bv[nf][1] = *(const uint32_t*)(cB + nr * SROWH + kh + 8);
            }
#pragma unroll
            for (int mf = 0; mf < MF; mf++)
#pragma unroll
                for (int nf = 0; nf < NF; nf++)
                    mma16816(acc[mf][nf], av[mf], bv[nf]);
        }

        if (more) {
            stsA(buf ^ 1); stsB(buf ^ 1);
            __syncthreads();
            buf ^= 1;
        }
    }

    // epilogue: c0=(g,2t) c1=(g,2t+1) c2=(g+8,2t) c3=(g+8,2t+1)
#pragma unroll
    for (int mf = 0; mf < MF; mf++)
#pragma unroll
        for (int nf = 0; nf < NF; nf++) {
            int m0 = bm + wm * WM + mf * 16 + gl;
            int n0 = bn + wn * WN + nf * 8 + tl * 2;
            float b0 = 0.f, b1 = 0.f;
            if (bias) { b0 = __ldg(bias + n0); b1 = __ldg(bias + n0 + 1); }
#pragma unroll
            for (int rr = 0; rr < 2; rr++) {
                int m = m0 + rr * 8;
                float v0 = acc[mf][nf][rr * 2 + 0] + b0;
                float v1 = acc[mf][nf][rr * 2 + 1] + b1;
                if (ACT == 1)      { v0 = tanhf(v0); v1 = tanhf(v1); }
                else if (ACT == 2) {
                    v0 = 0.5f * v0 * (1.f + erff(v0 * 0.7071067811865476f));
                    v1 = 0.5f * v1 * (1.f + erff(v1 * 0.7071067811865476f));
                }
                if (causal) { if (n0 > m) v0 = 0.f; if (n0 + 1 > m) v1 = 0.f; }
                if (rowscale) {
                    float rs = rsqrtf((float)(m + 1) * kf);
                    v0 *= rs; v1 *= rs;
                }
                if (resid) {
                    float2 rv = *(const float2*)(resid + (size_t)m * N + n0);
                    v0 += rv.x; v1 += rv.y;
                }
                if (resid2) {
                    float2 rv = *(const float2*)(resid2 + (size_t)m * N + n0);
                    v0 += rv.x; v1 += rv.y;
                }
                *(float2*)(C + (size_t)m * N + n0) = make_float2(v0, v1);
            }
        }
}

enum { ACT_NONE = 0, ACT_TANH = 1, ACT_GELU = 2, ACT_TANHPI = 3 };

// big: 128x128 tiles, 8 warps; mid: 64x64 tiles, 4 warps (R8 config)
template<int TRANSB, int ACT>
static void mm(const float* A, const float* Bp, float* C, int M, int N, int Kd,
               const float* bias, const float* resid, const float* resid2 = nullptr,
               int causal = 0, int rowscale = 0, float kf = 32.f,
               int gz = 1, long sAz = 0, long sBz = 0, long sCz = 0,
               int ktrunc = 0)
{
    long big_blocks = (long)(M / 128) * (N / 128) * gz;
    if (N % 128 == 0 && big_blocks >= 148) {
        constexpr int SM_BYTES = 2 * (128 + 128) * SROWH * 2;  // 40960
        dim3 g(N / 128, M / 128, gz);
        mma_gemm_k<128, 128, 32, 64, TRANSB, ACT><<<g, 256, SM_BYTES>>>(
            A, Bp, C, M, N, Kd, bias, resid, resid2, causal, rowscale, kf, ktrunc,
            sAz, sBz, sCz);
    } else {
        constexpr int SM_BYTES = 2 * (64 + 64) * SROWH * 2;    // 20480
        dim3 g(N / 64, M / 64, gz);
        mma_gemm_k<64, 64, 32, 32, TRANSB, ACT><<<g, 128, SM_BYTES>>>(
            A, Bp, C, M, N, Kd, bias, resid, resid2, causal, rowscale, kf, ktrunc,
            sAz, sBz, sCz);
    }
}

// ================== small helpers ================================
__device__ __forceinline__ float block_sum(float v, float* red) {
    int lane = threadIdx.x & 31, w = threadIdx.x >> 5;
#pragma unroll
    for (int o = 16; o; o >>= 1) v += __shfl_xor_sync(0xffffffffu, v, o);
    __syncthreads();
    if (lane == 0) red[w] = v;
    __syncthreads();
    float t = (threadIdx.x < (blockDim.x >> 5)) ? red[threadIdx.x] : 0.f;
    if (w == 0) {
#pragma unroll
        for (int o = 16; o; o >>= 1) t += __shfl_xor_sync(0xffffffffu, t, o);
        if (lane == 0) red[32] = t;
    }
    __syncthreads();
    return red[32];
}

// vectorized LayerNorm: Dn == 4*blockDim.x (D=512, 128 threads)
__global__ void ln_k(const float* __restrict__ X, float* __restrict__ Y,
                     const float* __restrict__ g, const float* __restrict__ b, int Dn)
{
    __shared__ float red[33];
    int row = blockIdx.x;
    float4 v = ((const float4*)(X + (size_t)row * Dn))[threadIdx.x];
    float s = v.x + v.y + v.z + v.w;
    float mean = block_sum(s, red) / (float)Dn;
    float dx = v.x - mean, dy = v.y - mean, dz = v.z - mean, dw = v.w - mean;
    float q = dx * dx + dy * dy + dz * dz + dw * dw;
    float var = block_sum(q, red) / (float)Dn;
    float inv = rsqrtf(var + 1e-5f);
    float4 g4 = ((const float4*)g)[threadIdx.x];
    float4 b4 = ((const float4*)b)[threadIdx.x];
    float4 o;
    o.x = dx * inv * g4.x + b4.x;
    o.y = dy * inv * g4.y + b4.y;
    o.z = dz * inv * g4.z + b4.z;
    o.w = dw * inv * g4.w + b4.w;
    ((float4*)(Y + (size_t)row * Dn))[threadIdx.x] = o;
}

__global__ void gather_k(const int* __restrict__ tok, const float* __restrict__ emb,
                         float* __restrict__ h, int n, int Dn)
{
    int i = blockIdx.x * blockDim.x + threadIdx.x;
    int total = n * (Dn / 4);
    if (i >= total) return;
    int row = i / (Dn / 4), c = i % (Dn / 4);
    ((float4*)h)[i] = ((const float4*)(emb + (size_t)tok[row] * Dn))[c];
}

// phase_k with fused split-K reduction + bias + pi*tanh:
// cp_raw = sum_z cp4[z*MK + i] + b2[k];  cp = pi*tanh(cp_raw)
__global__ void phase_k(const float* __restrict__ cp4, const float* __restrict__ b2,
                        float* __restrict__ cs,
                        const float* __restrict__ ps_arr, const float* __restrict__ cs_arr,
                        int layer, int Ln, int Kn, int total)
{
    int i = blockIdx.x * blockDim.x + threadIdx.x;
    if (i >= total) return;
    int k  = i % Kn;
    int l  = (i / Kn) % Ln;
    int bl = i / Kn;
    float s = cp4[i] + cp4[total + i] + cp4[2 * total + i] + cp4[3 * total + i] + b2[k];
    float cpv = 3.14159274101257324f * tanhf(s);
    float freq = (float)exp(-(double)k / (double)Kn * 9.210340371976184);
    float pos  = __fmul_rn((float)l, freq);
    float tp   = __fadd_rn(__fmul_rn(ps_arr[layer], pos),
                           __fmul_rn(cs_arr[layer], cpv));
    float* o = cs + (size_t)bl * (2 * Kn);
    o[k]      = cosf(tp);
    o[Kn + k] = sinf(tp);
}

// ---- fp32 split-K GEMM for cp_w2 (N=32): raw partials, 4-way K split ----
template<int BM, int BN, int BK, int TM, int TN>
__global__ void gemm_f32_splitk_k(const float* __restrict__ A, const float* __restrict__ Bp,
                                  float* __restrict__ C, int M, int N, int Kd, int split)
{
    constexpr int THREADS = (BM / TM) * (BN / TN);
    __shared__ float As[BK][BM + 4];
    __shared__ float Bs[BK][BN + 4];
    const int tid = threadIdx.x;
    const int bm = blockIdx.y * BM, bn = blockIdx.x * BN;
    const int z  = blockIdx.z;
    const int kslice = Kd / split;
    const int kbeg = z * kslice, kend = kbeg + kslice;
    const int tx = tid % (BN / TN), ty = tid / (BN / TN);

    float acc[TM][TN];
#pragma unroll
    for (int i = 0; i < TM; i++)
#pragma unroll
        for (int j = 0; j < TN; j++) acc[i][j] = 0.f;

    constexpr int A_IT = (BM * BK) / (4 * THREADS);
    constexpr int B_IT = (BK * BN) / (4 * THREADS);

    for (int k0 = kbeg; k0 < kend; k0 += BK) {
#pragma unroll
        for (int it = 0; it < A_IT; it++) {
            int t = tid + it * THREADS;
            int r = t / (BK / 4), c4 = (t % (BK / 4)) * 4;
            int m = bm + r;
            float4 v = make_float4(0.f, 0.f, 0.f, 0.f);
            if (m < M) v = *(const float4*)(A + (size_t)m * Kd + k0 + c4);
            As[c4 + 0][r] = v.x; As[c4 + 1][r] = v.y;
            As[c4 + 2][r] = v.z; As[c4 + 3][r] = v.w;
        }
#pragma unroll
        for (int it = 0; it < B_IT; it++) {
            int t = tid + it * THREADS;
            int kr = t / (BN / 4), nc = (t % (BN / 4)) * 4;
            float4 v = make_float4(0.f, 0.f, 0.f, 0.f);
            if (bn + nc < N) v = *(const float4*)(Bp + (size_t)(k0 + kr) * N + bn + nc);
            *(float4*)&Bs[kr][nc] = v;
        }
        __syncthreads();
#pragma unroll
        for (int kk = 0; kk < BK; kk++) {
            float a[TM], b[TN];
#pragma unroll
            for (int i = 0; i < TM; i++) a[i] = As[kk][ty * TM + i];
#pragma unroll
            for (int j = 0; j < TN; j++) b[j] = Bs[kk][tx * TN + j];
#pragma unroll
            for (int i = 0; i < TM; i++)
#pragma unroll
                for (int j = 0; j < TN; j++)
                    acc[i][j] = fmaf(a[i], b[j], acc[i][j]);
        }
        __syncthreads();
    }
    float* Cz = C + (size_t)z * M * N;
#pragma unroll
    for (int i = 0; i < TM; i++) {
        int m = bm + ty * TM + i;
        if (m >= M) continue;
#pragma unroll
        for (int j = 0; j < TN; j++) {
            int n = bn + tx * TN + j;
            if (n >= N) continue;
            Cz[(size_t)m * N + n] = acc[i][j];
        }
    }
}

// ---------------- orchestration ----------------
extern "C" void kernel_launch(void* const* d_in, const int* in_sizes, int n_in,
                              void* d_out, int out_size)
{
    using namespace cfg;
    const int*   tokens        = (const int*)  d_in[0];
    const float* embed         = (const float*)d_in[1];
    const float* ln1_g         = (const float*)d_in[2];
    const float* ln1_b         = (const float*)d_in[3];
    const float* cp_w1         = (const float*)d_in[4];
    const float* cp_b1         = (const float*)d_in[5];
    const float* cp_w2         = (const float*)d_in[6];
    const float* cp_b2         = (const float*)d_in[7];
    const float* pos_scale     = (const float*)d_in[8];
    const float* content_scale = (const float*)d_in[9];
    const float* val_w         = (const float*)d_in[10];
    const float* val_b         = (const float*)d_in[11];
    const float* oln_g         = (const float*)d_in[12];
    const float* oln_b         = (const float*)d_in[13];
    const float* out_w         = (const float*)d_in[14];
    const float* out_b         = (const float*)d_in[15];
    const float* ln2_g         = (const float*)d_in[16];
    const float* ln2_b         = (const float*)d_in[17];
    const float* ffn_w1        = (const float*)d_in[18];
    const float* ffn_b1        = (const float*)d_in[19];
    const float* ffn_w2        = (const float*)d_in[20];
    const float* ffn_b2        = (const float*)d_in[21];
    const float* no_g          = (const float*)d_in[22];
    const float* no_b          = (const float*)d_in[23];
    const float* head_b        = (const float*)d_in[24];
    float* out = (float*)d_out;

    float* base = nullptr;
    cudaGetSymbolAddress((void**)&base, g_scratch);
    float* h   = base + OFF_H;
    float* x   = base + OFF_X;
    float* t1  = base + OFF_T1;
    float* v   = base + OFF_V;
    float* ret = base + OFF_RET;
    float* r2  = base + OFF_R2;
    float* cp4 = base + OFF_CP4;
    float* cs  = base + OFF_CS;
    float* sc  = base + OFF_SC;
    float* f1  = base + OFF_F1;

    gather_k<<<(M * D / 4 + 255) / 256, 256>>>(tokens, embed, h, M, D);

    for (int i = 0; i < NL; i++) {
        ln_k<<<M, 128>>>(h, x, ln1_g + (size_t)i * D, ln1_b + (size_t)i * D, D);
        // t1 = tanh(x @ cp_w1 + b1)      [2048,512,512] -> mid 64x64, 256 blocks
        mm<0, ACT_TANH>(x, cp_w1 + (size_t)i * D * D, t1, M, D, D,
                        cp_b1 + (size_t)i * D, nullptr);
        // cp partials = t1 @ cp_w2 (split-K x4)   grid (1,64,4) = 256 blocks
        {
            dim3 g(K / 32, M / 32, 4);
            gemm_f32_splitk_k<32, 32, 32, 2, 2><<<g, 256>>>(
                t1, cp_w2 + (size_t)i * D * K, cp4, M, K, D, 4);
        }
        // v = x @ val_w + val_b
        mm<0, ACT_NONE>(x, val_w + (size_t)i * D * D, v, M, D, D,
                        val_b + (size_t)i * D, nullptr);
        // cs = [cos|sin] with fused split-K reduce + bias + pi*tanh
        phase_k<<<(B * L * K + 255) / 256, 256>>>(cp4, cp_b2 + (size_t)i * K, cs,
                                                  pos_scale, content_scale,
                                                  i, L, K, B * L * K);
        // scores = tril(P P^T)  [L,L,64] x2 -> mid 64x64, 512 blocks
        mm<1, ACT_NONE>(cs, cs, sc, L, L, CS, nullptr, nullptr, nullptr,
                        /*causal=*/1, 0, 0.f,
                        /*gz=*/B, (long)L * CS, (long)L * CS, (long)L * L);
        // ret = (scores @ v) * rsqrt((m+1)*K)  [L,D,L] x2 -> mid, 256 blocks
        // ktrunc: sc upper triangle is exact zero -> truncate K loop per row-block
        mm<0, ACT_NONE>(sc, v, ret, L, D, L, nullptr, nullptr, nullptr,
                        0, /*rowscale=*/1, (float)K,
                        /*gz=*/B, (long)L * L, (long)L * D, (long)L * D,
                        /*ktrunc=*/1);
        ln_k<<<M, 128>>>(ret, r2, oln_g + (size_t)i * D, oln_b + (size_t)i * D, D);
        // h = (h + x) + r2 @ out_w + out_b    (dual residual)
        mm<0, ACT_NONE>(r2, out_w + (size_t)i * D * D, h, M, D, D,
                        out_b + (size_t)i * D, h, x);
        ln_k<<<M, 128>>>(h, x, ln2_g + (size_t)i * D, ln2_b + (size_t)i * D, D);
        // f1 = gelu(x @ ffn_w1 + b1)   [2048,2048,512] -> big tiles, 256 blocks
        mm<0, ACT_GELU>(x, ffn_w1 + (size_t)i * D * FF, f1, M, FF, D,
                        ffn_b1 + (size_t)i * FF, nullptr);
        // h = h + f1 @ ffn_w2 + b2     [2048,512,2048] -> mid tiles
        mm<0, ACT_NONE>(f1, ffn_w2 + (size_t)i * FF * D, h, M, D, FF,
                        ffn_b2 + (size_t)i * D, h);
    }

    ln_k<<<M, 128>>>(h, x, no_g, no_b, D);
    // logits = LN(h) @ embed^T + head_b   [2048,32000,512] -> big tiles
    mm<1, ACT_NONE>(x, embed, out, M, V, D, head_b, nullptr);
}